// round 13
// baseline (speedup 1.0000x reference)
#include <cuda_runtime.h>
#include <cuda_fp16.h>

#define BS 64
#define G 360
#define V 100
#define D 32
#define U 512
#define T 15
#define VOC 5000
#define VOCP 5120
#define TD 512
#define H 8
#define E 544          // D + U
#define HD 68          // E / H
#define NEG 0.2f
#define INV_S 0.12126781251816648f   // 1/sqrt(68)
#define XDIM 1056      // E + U
#define XH 528         // XDIM/2 (split-K half)
#define R4U 2048       // 4*U

// ----------------------------- device scratch -----------------------------
__device__ float  g_feat[BS*G*D];
__device__ float  g_qf[(size_t)BS*G*E];
__device__ float  g_kf[(size_t)BS*G*E];
__device__ __half g_Ebuf[(size_t)BS*H*G*G];   // fp16 exp(A), shift-free
__device__ float  g_WqaT[U*E];
__device__ float  g_Wcat[(size_t)XDIM*R4U];
__device__ float  g_bias[R4U];
__device__ float  g_W2T[256*VOCP];            // fp32 W2^T, padded tail zeroed
__device__ float  g_wpart[BS*H*G];
__device__ float  g_ctxp[BS*H*D];             // per-head partial ctx
__device__ float  g_qa[BS*E];
__device__ float  g_gates[BS*R4U];
__device__ float  g_gates2[BS*R4U];
__device__ float  g_ab[2*BS*U];               // double-buffered hidden state a
__device__ float  g_c[BS*U];
__device__ float  g_h1[BS*256];
__device__ float  g_logits[BS*VOC];

__device__ __forceinline__ float sigmoidf_(float x){ return 1.f/(1.f+__expf(-x)); }
__device__ __forceinline__ float leakyf_(float x){ return x > 0.f ? x : NEG*x; }

__device__ __forceinline__ float fexp_(float x){
    float t = x * 1.4426950408889634f;
    float r = rintf(t);
    float f = t - r;
    float p =          1.3333558e-3f;
    p = fmaf(p, f, 9.6181291e-3f);
    p = fmaf(p, f, 5.5504109e-2f);
    p = fmaf(p, f, 2.4022651e-1f);
    p = fmaf(p, f, 6.9314718e-1f);
    p = fmaf(p, f, 1.0f);
    int ei = (int)r;
    if (ei < -126) ei = -126;
    return p * __int_as_float((ei + 127) << 23);
}

// ---------------------- encoder: feat = lrelu(LN(x@W+b)) -------------------
__global__ void k_encoder(const float* __restrict__ features, const float* __restrict__ enc_W,
                          const float* __restrict__ enc_b, const float* __restrict__ enc_g,
                          const float* __restrict__ enc_beta){
    int g = blockIdx.x;
    int tid = threadIdx.x;               // 256
    int warp = tid >> 5, lane = tid & 31;
    __shared__ float Ws[D*101];
    __shared__ float bs_[D];
    __shared__ float xw[8][V];
    for (int k = tid; k < D*V; k += 256){
        int d = k / V, v = k - d*V;
        Ws[d*101 + v] = enc_W[(size_t)g*D*V + k];
    }
    if (tid < D) bs_[tid] = enc_b[g*D + tid];
    __syncthreads();
    float gg = enc_g[lane], bb = enc_beta[lane];
    for (int b = warp; b < BS; b += 8){
        for (int v = lane; v < V; v += 32) xw[warp][v] = features[((size_t)b*G + g)*V + v];
        __syncwarp();
        const float* w = Ws + lane*101;
        float acc = bs_[lane];
        #pragma unroll 4
        for (int v = 0; v < V; v++) acc = fmaf(xw[warp][v], w[v], acc);
        float m = acc;
        #pragma unroll
        for (int o=16;o;o>>=1) m += __shfl_xor_sync(0xffffffffu, m, o);
        m *= (1.f/32.f);
        float dv = acc - m, vv = dv*dv;
        #pragma unroll
        for (int o=16;o;o>>=1) vv += __shfl_xor_sync(0xffffffffu, vv, o);
        vv *= (1.f/32.f);
        float y = dv*rsqrtf(vv+1e-5f)*gg + bb;
        g_feat[((size_t)b*G + g)*D + lane] = leakyf_(y);
        __syncwarp();
    }
}

// ---------------- qf / kf projections (weights in registers) ---------------
__global__ void k_qkf(const float* __restrict__ in_w){
    int mat = blockIdx.y >> 1;
    int eh  = blockIdx.y & 1;
    int le  = threadIdx.x;               // 0..271
    int ebase = eh*272;
    __shared__ float Ws[272*33];
    __shared__ float fs[60*32];
    for (int k = le; k < 272*32; k += 272){
        int i = k >> 5, d = k & 31;
        Ws[i*33 + d] = in_w[((size_t)(mat*E + ebase + i))*E + d];
    }
    int r0 = blockIdx.x*60;
    for (int k = le; k < 60*32; k += 272)
        fs[k] = g_feat[(size_t)r0*D + k];
    __syncthreads();
    float w[32];
    #pragma unroll
    for (int d = 0; d < 32; d++) w[d] = Ws[le*33 + d];
    float* dst = (mat == 0 ? g_qf : g_kf);
    #pragma unroll 2
    for (int rr = 0; rr < 60; rr++){
        float acc = 0.f;
        #pragma unroll
        for (int d = 0; d < 32; d++) acc = fmaf(fs[rr*32 + d], w[d], acc);
        dst[(size_t)(r0 + rr)*E + ebase + le] = acc;
    }
}

// -------- coalesced weight transposes (32x32 smem tiles, z = matrix) --------
__global__ void k_prepT(const float* __restrict__ in_w, const float* __restrict__ Wih,
                        const float* __restrict__ Whh, const float* __restrict__ W2){
    __shared__ float tile[32][33];
    int zz = blockIdx.z;
    int c0 = blockIdx.x*32, r0 = blockIdx.y*32;
    int tx = threadIdx.x, ty = threadIdx.y;  // 32 x 8
    int R, C, ld, off, dstld;
    const float* src; float* dst;
    if (zz == 0){ R = E;   C = U;   src = in_w; ld = E;   off = D; dst = g_WqaT;           dstld = E;   }
    else if (zz == 1){ R = R4U; C = E; src = Wih; ld = E; off = 0; dst = g_Wcat;           dstld = R4U; }
    else if (zz == 2){ R = R4U; C = U; src = Whh; ld = U; off = 0; dst = g_Wcat + (size_t)E*R4U; dstld = R4U; }
    else { R = VOC; C = 256; src = W2;  ld = 256; off = 0; dst = g_W2T;                    dstld = VOCP; }
    if (r0 >= R || c0 >= C) return;
    for (int i = ty; i < 32; i += 8){
        int r = r0 + i, c = c0 + tx;
        if (r < R && c < C) tile[i][tx] = src[(size_t)r*ld + off + c];
    }
    __syncthreads();
    for (int i = ty; i < 32; i += 8){
        int c = c0 + i, r = r0 + tx;
        if (c < C && r < R) dst[(size_t)c*dstld + r] = tile[tx][i];
    }
}

// -------- small prep: bias sum, a/c init, W2T pad-zero ----------------------
__global__ void k_prepS(const float* __restrict__ bih, const float* __restrict__ bhh,
                        const float* __restrict__ a0, const float* __restrict__ c0){
    int i = blockIdx.x*256 + threadIdx.x;
    if (i < R4U) g_bias[i] = bih[i] + bhh[i];
    if (i < BS*U){ g_ab[i] = a0[i]; g_c[i] = c0[i]; }
    if (i < 256*(VOCP-VOC)){
        int k = i / (VOCP-VOC), v = VOC + (i - k*(VOCP-VOC));
        g_W2T[(size_t)k*VOCP + v] = 0.f;
    }
}

// -------- initial qa seed: qa = a0 @ WqaT + bq (after prepT on sB) ----------
__global__ void k_qa0(const float* __restrict__ a0, const float* __restrict__ in_b){
    int b = blockIdx.x;
    int e = threadIdx.x;                 // 544
    __shared__ float as_[U];
    if (e < U) as_[e] = a0[b*U + e];
    __syncthreads();
    float acc = in_b[e];
    #pragma unroll 8
    for (int u = 0; u < U; u++) acc = fmaf(as_[u], g_WqaT[(size_t)u*E + e], acc);
    g_qa[b*E + e] = acc;
}

// -- A-GEMM (HFMA2) with exp epilogue: E[b,h,i,j] = exp(qf.kf/sqrt(HD)) fp16 -
__global__ void k_aexp(){
    int bh = blockIdx.z; int b = bh >> 3, h = bh & 7;
    int i0 = blockIdx.y << 6, j0 = blockIdx.x << 6;
    __shared__ __half2 Qs[34*68];
    __shared__ __half2 Ks[34*68];
    int tid = threadIdx.x;             // 256
    const float* qbase = g_qf + (size_t)(b*G)*E + h*HD;
    for (int k = tid; k < 64*34; k += 256){
        int ii = k / 34, dp = k - ii*34;
        int gi = i0 + ii;
        float x0 = 0.f, x1 = 0.f;
        if (gi < G){
            x0 = qbase[(size_t)gi*E + 2*dp];
            x1 = qbase[(size_t)gi*E + 2*dp + 1];
        }
        Qs[dp*68 + ii] = __floats2half2_rn(x0, x1);
    }
    const float* kbase = g_kf + (size_t)(b*G)*E + h*HD;
    for (int k = tid; k < 64*34; k += 256){
        int jj = k / 34, dp = k - jj*34;
        int gj = j0 + jj;
        float x0 = 0.f, x1 = 0.f;
        if (gj < G){
            x0 = kbase[(size_t)gj*E + 2*dp];
            x1 = kbase[(size_t)gj*E + 2*dp + 1];
        }
        Ks[dp*68 + jj] = __floats2half2_rn(x0, x1);
    }
    __syncthreads();
    int tx = tid & 15, ty = tid >> 4;
    __half2 acc[4][4];
    #pragma unroll
    for (int r = 0; r < 4; r++)
        #pragma unroll
        for (int c = 0; c < 4; c++) acc[r][c] = __floats2half2_rn(0.f, 0.f);
    #pragma unroll 2
    for (int dp = 0; dp < 34; dp++){
        float4 qv = *(const float4*)&Qs[dp*68 + (ty<<2)];
        float4 kv = *(const float4*)&Ks[dp*68 + (tx<<2)];
        __half2 q2[4], k2[4];
        q2[0] = *(__half2*)&qv.x; q2[1] = *(__half2*)&qv.y;
        q2[2] = *(__half2*)&qv.z; q2[3] = *(__half2*)&qv.w;
        k2[0] = *(__half2*)&kv.x; k2[1] = *(__half2*)&kv.y;
        k2[2] = *(__half2*)&kv.z; k2[3] = *(__half2*)&kv.w;
        #pragma unroll
        for (int r = 0; r < 4; r++)
            #pragma unroll
            for (int c = 0; c < 4; c++) acc[r][c] = __hfma2(q2[r], k2[c], acc[r][c]);
    }
    #pragma unroll
    for (int r = 0; r < 4; r++){
        int i = i0 + (ty<<2) + r;
        if (i >= G) continue;
        __half* row = g_Ebuf + ((size_t)bh*G + i)*G;
        #pragma unroll
        for (int c = 0; c < 4; c += 2){
            int j = j0 + (tx<<2) + c;
            float a0v = __low2float(acc[r][c])   + __high2float(acc[r][c]);
            float a1v = __low2float(acc[r][c+1]) + __high2float(acc[r][c+1]);
            if (j + 1 < G){
                *(__half2*)(row + j) = __floats2half2_rn(fexp_(a0v*INV_S), fexp_(a1v*INV_S));
            } else if (j < G){
                row[j] = __float2half(fexp_(a0v*INV_S));
            }
        }
    }
}

// ---- per-step attention: e + E-pass + per-head partial ctx (qa ready) -----
__global__ void k_att(){
    int bh = blockIdx.x; int b = bh >> 3, h = bh & 7;
    int tid = threadIdx.x;               // 384
    int warp = tid >> 5, lane = tid & 31;
    __shared__ float qs[HD];
    __shared__ float es[G];
    __shared__ float wp_s[G];
    __shared__ float colsum[12][G];
    cudaGridDependencySynchronize();     // wait for lstm(t-1)'s qa
    if (tid < HD) qs[tid] = g_qa[b*E + h*HD + tid];
    __syncthreads();
    for (int jr = warp; jr < G; jr += 12){
        const float* kfr = g_kf + ((size_t)(b*G + jr))*E + h*HD;
        float p = kfr[lane]*qs[lane] + kfr[lane+32]*qs[lane+32];
        if (lane < 4) p = fmaf(kfr[64+lane], qs[64+lane], p);
        #pragma unroll
        for (int o=16;o;o>>=1) p += __shfl_xor_sync(0xffffffffu, p, o);
        if (lane == 0) es[jr] = fexp_(p * INV_S);
    }
    __syncthreads();
    float racc[12];
    #pragma unroll
    for (int k = 0; k < 12; k++) racc[k] = 0.f;
    const __half2* Eb = (const __half2*)(g_Ebuf + (size_t)bh*G*G);
    const float2* es2 = (const float2*)es;
    for (int i = warp*2; i < G; i += 24){
        const __half2* r0p = Eb + (size_t)i*(G/2);
        const __half2* r1p = r0p + (G/2);
        float2 f0[6], f1[6];
        float d0 = 0.f, d1 = 0.f;
        #pragma unroll
        for (int s = 0; s < 6; s++){
            int jj = lane + 32*s;
            if (jj < G/2){
                f0[s] = __half22float2(r0p[jj]);
                f1[s] = __half22float2(r1p[jj]);
                float2 e2 = es2[jj];
                d0 = fmaf(f0[s].x, e2.x, d0);
                d0 = fmaf(f0[s].y, e2.y, d0);
                d1 = fmaf(f1[s].x, e2.x, d1);
                d1 = fmaf(f1[s].y, e2.y, d1);
            } else {
                f0[s].x = 0.f; f0[s].y = 0.f;
                f1[s].x = 0.f; f1[s].y = 0.f;
            }
        }
        #pragma unroll
        for (int o=16;o;o>>=1){
            d0 += __shfl_xor_sync(0xffffffffu, d0, o);
            d1 += __shfl_xor_sync(0xffffffffu, d1, o);
        }
        float rinv0 = 1.f/d0, rinv1 = 1.f/d1;
        #pragma unroll
        for (int s = 0; s < 6; s++){
            racc[2*s]   = fmaf(f0[s].x, rinv0, fmaf(f1[s].x, rinv1, racc[2*s]));
            racc[2*s+1] = fmaf(f0[s].y, rinv0, fmaf(f1[s].y, rinv1, racc[2*s+1]));
        }
    }
    #pragma unroll
    for (int s = 0; s < 6; s++){
        int jj = lane + 32*s;
        if (jj < G/2){
            colsum[warp][2*jj]   = racc[2*s];
            colsum[warp][2*jj+1] = racc[2*s+1];
        }
    }
    __syncthreads();
    if (tid < G){
        float tot = 0.f;
        #pragma unroll
        for (int w = 0; w < 12; w++) tot += colsum[w][tid];
        float wv = es[tid]*tot;
        wp_s[tid] = wv;
        g_wpart[bh*G + tid] = wv;
    }
    __syncthreads();
    {
        int j0 = warp*30;
        const float* fp = g_feat + ((size_t)b*G + j0)*D + lane;
        float acc = 0.f;
        #pragma unroll 5
        for (int j = 0; j < 30; j++) acc = fmaf(wp_s[j0 + j], fp[(size_t)j*D], acc);
        colsum[warp][lane] = acc;
    }
    __syncthreads();
    if (tid < D){
        float s = 0.f;
        #pragma unroll
        for (int k = 0; k < 12; k++) s += colsum[k][tid];
        g_ctxp[bh*D + tid] = s;
    }
}

// ---- per-step: gate GEMM + (z=0) w-scores out + ctx-from-partials ----------
// PDL: emb/token fills run BEFORE the dependency sync (overlap with k_att).
__global__ void k_gates(const int* __restrict__ text, const float* __restrict__ emb,
                        float* __restrict__ out, int t, int par){
    int z  = blockIdx.z;
    int b0 = blockIdx.y*8;
    int tid = threadIdx.x;               // 128
    int r = blockIdx.x*128 + tid;        // grid.x = 16
    __shared__ float xs[8][XH];
    int x0 = z*XH;
    const float* ga = g_ab + (size_t)par*BS*U;
    // --- prologue: predecessor-independent fills ---
    if (z == 0){
        for (int bb = 0; bb < 8; bb++){
            int tok = text[(b0+bb)*T + t];
            for (int xx = tid; xx < XH; xx += 128)
                if (xx >= D) xs[bb][xx] = emb[(size_t)tok*TD + (xx - D)];
        }
    } else {
        for (int bb = 0; bb < 8; bb++){
            int tok = text[(b0+bb)*T + t];
            for (int xx = tid; xx < 16; xx += 128)   // x in [XH, E)
                xs[bb][xx] = emb[(size_t)tok*TD + (x0 + xx - D)];
        }
    }
    cudaGridDependencySynchronize();     // wait for k_att's wpart/ctxp (and a)
    if (z == 0){
        if (blockIdx.x == 0){
            for (int idx = tid; idx < 8*G; idx += 128){
                int bb = idx / G, j = idx - bb*G;
                const float* p = g_wpart + (size_t)(b0+bb)*H*G + j;
                float acc = 0.f;
                #pragma unroll
                for (int hh = 0; hh < H; hh++) acc += p[hh*G];
                out[(size_t)BS*T*VOC + ((size_t)(b0+bb)*T + t)*G + j] = acc * (1.f/(float)(H*G));
            }
        }
        for (int pr = tid; pr < 256; pr += 128){
            int bb = pr >> 5, d = pr & 31;
            const float* cp = g_ctxp + (size_t)(b0+bb)*H*D + d;
            float acc = 0.f;
            #pragma unroll
            for (int hh = 0; hh < H; hh++) acc += cp[hh*D];
            xs[bb][d] = acc * (1.f/(float)(H*G));
        }
    } else {
        for (int bb = 0; bb < 8; bb++){
            int b = b0 + bb;
            for (int xx = tid; xx < XH; xx += 128)
                if (xx >= 16) xs[bb][xx] = ga[b*U + (x0 + xx - E)];
        }
    }
    __syncthreads();
    float acc[8] = {};
    const float* wp = g_Wcat + (size_t)x0*R4U + r;
    #pragma unroll 4
    for (int xx = 0; xx < XH; xx++){
        float w = wp[(size_t)xx*R4U];
        #pragma unroll
        for (int bb = 0; bb < 8; bb++) acc[bb] = fmaf(xs[bb][xx], w, acc[bb]);
    }
    float* dst = (z == 0) ? g_gates : g_gates2;
    #pragma unroll
    for (int bb = 0; bb < 8; bb++) dst[(size_t)(b0+bb)*R4U + r] = acc[bb];
}

// ---- per-step LSTM cell + LN + next-step qa (critical path) ---------------
__global__ void k_lstm(const float* __restrict__ ln_g, const float* __restrict__ ln_b,
                       const float* __restrict__ in_b, int outpar){
    int b = blockIdx.x, tid = threadIdx.x;   // 512
    __shared__ float araw[U];
    __shared__ float r1[16], r2[16];
    cudaGridDependencySynchronize();         // wait for k_gates
    int u = tid;
    const float* gr0 = g_gates  + (size_t)b*R4U;
    const float* gr1 = g_gates2 + (size_t)b*R4U;
    float gi = gr0[u]       + gr1[u]       + g_bias[u];
    float gf = gr0[U+u]     + gr1[U+u]     + g_bias[U+u];
    float gg = gr0[2*U+u]   + gr1[2*U+u]   + g_bias[2*U+u];
    float go = gr0[3*U+u]   + gr1[3*U+u]   + g_bias[3*U+u];
    float c = sigmoidf_(gf)*g_c[b*U+u] + sigmoidf_(gi)*tanhf(gg);
    g_c[b*U+u] = c;
    float hh = sigmoidf_(go)*tanhf(c);
    float s1 = hh, s2 = hh*hh;
    #pragma unroll
    for (int o=16;o;o>>=1){ s1 += __shfl_xor_sync(0xffffffffu,s1,o); s2 += __shfl_xor_sync(0xffffffffu,s2,o); }
    int w = tid>>5, l = tid&31;
    if (l==0){ r1[w]=s1; r2[w]=s2; }
    __syncthreads();
    if (tid==0){
        float t1=0.f, t2=0.f;
        #pragma unroll
        for (int i=0;i<16;i++){ t1+=r1[i]; t2+=r2[i]; }
        r1[0]=t1; r2[0]=t2;
    }
    __syncthreads();
    float m = r1[0]*(1.f/(float)U);
    float var = r2[0]*(1.f/(float)U) - m*m;
    float a = (hh-m)*rsqrtf(var+1e-5f)*ln_g[u]+ln_b[u];
    g_ab[(size_t)outpar*BS*U + b*U + u] = a;
    araw[u] = a;
    __syncthreads();
    // next-step qa: qa[e] = sum_u a[u]*WqaT[u][e] + bq[e]
    for (int e = tid; e < E; e += 512){
        float acc = in_b[e];
        #pragma unroll 8
        for (int uu = 0; uu < U; uu++) acc = fmaf(araw[uu], g_WqaT[(size_t)uu*E + e], acc);
        g_qa[b*E + e] = acc;
    }
}

// ------------- per-step MLP layer 1 (on stream B) ---------------------------
__global__ void k_mlp1(const float* __restrict__ W1, const float* __restrict__ b1, int par){
    int b = blockIdx.x, tid = threadIdx.x;   // 512
    __shared__ float sact[U];
    cudaGridDependencySynchronize();
    sact[tid] = leakyf_(g_ab[(size_t)par*BS*U + b*U + tid]);
    __syncthreads();
    int w = tid>>5, l = tid&31;
    #pragma unroll
    for (int kk = 0; kk < 16; kk++){
        int k = w*16 + kk;
        const float* wrow = W1 + (size_t)k*U;
        float acc = 0.f;
        #pragma unroll 4
        for (int uu = l; uu < U; uu += 32) acc = fmaf(sact[uu], wrow[uu], acc);
        #pragma unroll
        for (int o=16;o;o>>=1) acc += __shfl_xor_sync(0xffffffffu, acc, o);
        if (l==0) g_h1[b*256+k] = leakyf_(acc + b1[k]);
    }
}

// ------------- per-step MLP layer 2 (register-blocked GEMM) ----------------
__global__ void k_mlp2(const float* __restrict__ b2){
    int v0 = blockIdx.x*64;
    int b0 = blockIdx.y*32;
    int tid = threadIdx.x;                   // 256
    int tx = tid & 31, ty = tid >> 5;
    __shared__ float h1T[256*36];
    cudaGridDependencySynchronize();
    for (int i = tid; i < 256*32; i += 256){
        int k = i & 255, bb = i >> 8;
        h1T[k*36 + bb] = g_h1[(size_t)(b0+bb)*256 + k];
    }
    __syncthreads();
    int v = v0 + tx*2;
    float acc[2][4] = {};
    const float* w2 = g_W2T + v;
    const float* hp = h1T + ty*4;
    #pragma unroll 4
    for (int k = 0; k < 256; k++){
        float2 w = *(const float2*)(w2 + (size_t)k*VOCP);
        float4 hv = *(const float4*)(hp + k*36);
        acc[0][0] = fmaf(w.x, hv.x, acc[0][0]);
        acc[0][1] = fmaf(w.x, hv.y, acc[0][1]);
        acc[0][2] = fmaf(w.x, hv.z, acc[0][2]);
        acc[0][3] = fmaf(w.x, hv.w, acc[0][3]);
        acc[1][0] = fmaf(w.y, hv.x, acc[1][0]);
        acc[1][1] = fmaf(w.y, hv.y, acc[1][1]);
        acc[1][2] = fmaf(w.y, hv.z, acc[1][2]);
        acc[1][3] = fmaf(w.y, hv.w, acc[1][3]);
    }
    float bv0 = (v < VOC)   ? b2[v]   : 0.f;
    float bv1 = (v+1 < VOC) ? b2[v+1] : 0.f;
    #pragma unroll
    for (int bb = 0; bb < 4; bb++){
        int b = b0 + ty*4 + bb;
        if (v < VOC)   g_logits[(size_t)b*VOC + v]   = acc[0][bb] + bv0;
        if (v+1 < VOC) g_logits[(size_t)b*VOC + v+1] = acc[1][bb] + bv1;
    }
}

// ------------- per-step softmax over VOC -----------------------------------
__global__ void k_soft(float* __restrict__ out, int t){
    int b = blockIdx.x, tid = threadIdx.x;   // 512
    __shared__ float buf[VOC];
    __shared__ float red[16];
    cudaGridDependencySynchronize();
    float m = -1e30f;
    for (int v = tid; v < VOC; v += 512){
        float x = g_logits[(size_t)b*VOC+v];
        buf[v] = x;
        m = fmaxf(m, x);
    }
    #pragma unroll
    for (int o=16;o;o>>=1) m = fmaxf(m, __shfl_xor_sync(0xffffffffu,m,o));
    if ((tid&31)==0) red[tid>>5]=m;
    __syncthreads();
    if (tid==0){ float mm=red[0]; for(int i=1;i<16;i++) mm=fmaxf(mm,red[i]); red[0]=mm; }
    __syncthreads();
    m = red[0];
    __syncthreads();
    float s = 0.f;
    for (int v = tid; v < VOC; v += 512){
        float e = fexp_(buf[v]-m);
        buf[v] = e;
        s += e;
    }
    #pragma unroll
    for (int o=16;o;o>>=1) s += __shfl_xor_sync(0xffffffffu,s,o);
    if ((tid&31)==0) red[tid>>5]=s;
    __syncthreads();
    if (tid==0){ float ss=0.f; for(int i=0;i<16;i++) ss+=red[i]; red[0]=1.f/ss; }
    __syncthreads();
    float inv = red[0];
    float* orow = out + ((size_t)b*T + t)*VOC;
    for (int v = tid; v < VOC; v += 512) orow[v] = buf[v]*inv;
}

// ---------------------------------------------------------------------------
template<typename F, typename... A>
static inline void pdl_launch(F f, dim3 g, dim3 b, cudaStream_t st, A... args){
    cudaLaunchConfig_t cfg = {};
    cfg.gridDim = g; cfg.blockDim = b; cfg.dynamicSmemBytes = 0; cfg.stream = st;
    cudaLaunchAttribute at[1];
    at[0].id = cudaLaunchAttributeProgrammaticStreamSerialization;
    at[0].val.programmaticStreamSerializationAllowed = 1;
    cfg.attrs = at; cfg.numAttrs = 1;
    cudaLaunchKernelEx(&cfg, f, args...);
}

extern "C" void kernel_launch(void* const* d_in, const int* in_sizes, int n_in,
                              void* d_out, int out_size){
    const float* features = (const float*)d_in[0];
    const int*   text     = (const int*)  d_in[1];
    const float* a0       = (const float*)d_in[2];
    const float* c0       = (const float*)d_in[3];
    const float* enc_W    = (const float*)d_in[4];
    const float* enc_b    = (const float*)d_in[5];
    const float* enc_g    = (const float*)d_in[6];
    const float* enc_beta = (const float*)d_in[7];
    const float* emb      = (const float*)d_in[8];
    const float* in_w     = (const float*)d_in[9];
    const float* in_b     = (const float*)d_in[10];
    const float* Wih      = (const float*)d_in[11];
    const float* Whh      = (const float*)d_in[12];
    const float* bih      = (const float*)d_in[13];
    const float* bhh      = (const float*)d_in[14];
    const float* ln_g     = (const float*)d_in[15];
    const float* ln_b     = (const float*)d_in[16];
    const float* W1       = (const float*)d_in[17];
    const float* b1       = (const float*)d_in[18];
    const float* W2       = (const float*)d_in[19];
    const float* b2       = (const float*)d_in[20];
    float* out = (float*)d_out;
    (void)in_sizes; (void)n_in; (void)out_size;

    cudaStream_t s0 = 0, sB;
    cudaStreamCreateWithFlags(&sB, cudaStreamNonBlocking);
    cudaEvent_t evF, evP, evL, evE, evQ0, evQ1;
    cudaEventCreateWithFlags(&evF, cudaEventDisableTiming);
    cudaEventCreateWithFlags(&evP, cudaEventDisableTiming);
    cudaEventCreateWithFlags(&evL, cudaEventDisableTiming);
    cudaEventCreateWithFlags(&evE, cudaEventDisableTiming);
    cudaEventCreateWithFlags(&evQ0, cudaEventDisableTiming);
    cudaEventCreateWithFlags(&evQ1, cudaEventDisableTiming);

    cudaEventRecord(evF, s0);
    cudaStreamWaitEvent(sB, evF, 0);

    k_encoder<<<G, 256, 0, s0>>>(features, enc_W, enc_b, enc_g, enc_beta);   // 0
    k_qkf<<<dim3(BS*G/60, 4), 272, 0, s0>>>(in_w);                           // 1
    k_prepT<<<dim3(17, 157, 4), dim3(32, 8), 0, sB>>>(in_w, Wih, Whh, W2);   // 2
    k_aexp<<<dim3(6, 6, BS*H), 256, 0, s0>>>();                              // 3 (profiled)
    k_prepS<<<(BS*U + 255)/256, 256, 0, sB>>>(bih, bhh, a0, c0);             // 4
    k_qa0<<<BS, E, 0, sB>>>(a0, in_b);                                       // 5
    cudaEventRecord(evP, sB);
    cudaStreamWaitEvent(s0, evP, 0);

    for (int t = 0; t < T; t++){
        int par = t & 1, npar = (t + 1) & 1;
        pdl_launch(k_att, dim3(BS*H), dim3(384), s0);
        pdl_launch(k_gates, dim3(16, 8, 2), dim3(128), s0, text, emb, out, t, par);
        // WAR: lstm(t) writes a-buffer npar, read by mlp1(t-2) (same parity)
        if (t >= 2) cudaStreamWaitEvent(s0, (par == 0) ? evQ0 : evQ1, 0);
        pdl_launch(k_lstm, dim3(BS), dim3(512), s0, ln_g, ln_b, in_b, npar);
        cudaEventRecord(evL, s0);
        cudaStreamWaitEvent(sB, evL, 0);
        pdl_launch(k_mlp1, dim3(BS), dim3(512), sB, W1, b1, npar);
        cudaEventRecord((par == 0) ? evQ0 : evQ1, sB);
        pdl_launch(k_mlp2, dim3((VOC+63)/64, 2), dim3(256), sB, b2);
        pdl_launch(k_soft, dim3(BS), dim3(512), sB, out, t);
    }
    cudaEventRecord(evE, sB);
    cudaStreamWaitEvent(s0, evE, 0);
}

// round 14
// speedup vs baseline: 1.1060x; 1.1060x over previous
#include <cuda_runtime.h>
#include <cuda_fp16.h>
#include <mma.h>
using namespace nvcuda;

#define BS 64
#define G 360
#define V 100
#define D 32
#define U 512
#define T 15
#define VOC 5000
#define VOCP 5120
#define TD 512
#define H 8
#define E 544          // D + U
#define HD 68          // E / H
#define NEG 0.2f
#define INV_S 0.12126781251816648f   // 1/sqrt(68)
#define XDIM 1056      // E + U
#define XH 528         // XDIM/2 (split-K half)
#define R4U 2048       // 4*U

// ----------------------------- device scratch -----------------------------
__device__ float  g_feat[BS*G*D];
__device__ float  g_qf[(size_t)BS*G*E];
__device__ float  g_kf[(size_t)BS*G*E];
__device__ __half g_Ebuf[(size_t)BS*H*G*G];   // fp16 exp(A), shift-free
__device__ float  g_WqaT[U*E];
__device__ float  g_Wcat[(size_t)XDIM*R4U];
__device__ float  g_bias[R4U];
__device__ float  g_W2T[256*VOCP];            // fp32 W2^T, padded tail zeroed
__device__ float  g_wpart[BS*H*G];
__device__ float  g_ctxp[BS*H*D];             // per-head partial ctx
__device__ float  g_gates[BS*R4U];
__device__ float  g_gates2[BS*R4U];
__device__ float  g_ab[2*BS*U];               // double-buffered hidden state a
__device__ float  g_c[BS*U];
__device__ float  g_h1[BS*256];
__device__ float  g_logits[BS*VOC];

__device__ __forceinline__ float sigmoidf_(float x){ return 1.f/(1.f+__expf(-x)); }
__device__ __forceinline__ float leakyf_(float x){ return x > 0.f ? x : NEG*x; }

__device__ __forceinline__ float fexp_(float x){
    float t = x * 1.4426950408889634f;
    float r = rintf(t);
    float f = t - r;
    float p =          1.3333558e-3f;
    p = fmaf(p, f, 9.6181291e-3f);
    p = fmaf(p, f, 5.5504109e-2f);
    p = fmaf(p, f, 2.4022651e-1f);
    p = fmaf(p, f, 6.9314718e-1f);
    p = fmaf(p, f, 1.0f);
    int ei = (int)r;
    if (ei < -126) ei = -126;
    return p * __int_as_float((ei + 127) << 23);
}

// ---------------------- encoder: feat = lrelu(LN(x@W+b)) -------------------
__global__ void k_encoder(const float* __restrict__ features, const float* __restrict__ enc_W,
                          const float* __restrict__ enc_b, const float* __restrict__ enc_g,
                          const float* __restrict__ enc_beta){
    int g = blockIdx.x;
    int tid = threadIdx.x;               // 256
    int warp = tid >> 5, lane = tid & 31;
    __shared__ float Ws[D*101];
    __shared__ float bs_[D];
    __shared__ float xw[8][V];
    for (int k = tid; k < D*V; k += 256){
        int d = k / V, v = k - d*V;
        Ws[d*101 + v] = enc_W[(size_t)g*D*V + k];
    }
    if (tid < D) bs_[tid] = enc_b[g*D + tid];
    __syncthreads();
    float gg = enc_g[lane], bb = enc_beta[lane];
    for (int b = warp; b < BS; b += 8){
        for (int v = lane; v < V; v += 32) xw[warp][v] = features[((size_t)b*G + g)*V + v];
        __syncwarp();
        const float* w = Ws + lane*101;
        float acc = bs_[lane];
        #pragma unroll 4
        for (int v = 0; v < V; v++) acc = fmaf(xw[warp][v], w[v], acc);
        float m = acc;
        #pragma unroll
        for (int o=16;o;o>>=1) m += __shfl_xor_sync(0xffffffffu, m, o);
        m *= (1.f/32.f);
        float dv = acc - m, vv = dv*dv;
        #pragma unroll
        for (int o=16;o;o>>=1) vv += __shfl_xor_sync(0xffffffffu, vv, o);
        vv *= (1.f/32.f);
        float y = dv*rsqrtf(vv+1e-5f)*gg + bb;
        g_feat[((size_t)b*G + g)*D + lane] = leakyf_(y);
        __syncwarp();
    }
}

// ---------------- qf / kf projections (weights in registers) ---------------
__global__ void k_qkf(const float* __restrict__ in_w){
    int mat = blockIdx.y >> 1;
    int eh  = blockIdx.y & 1;
    int le  = threadIdx.x;               // 0..271
    int ebase = eh*272;
    __shared__ float Ws[272*33];
    __shared__ float fs[60*32];
    for (int k = le; k < 272*32; k += 272){
        int i = k >> 5, d = k & 31;
        Ws[i*33 + d] = in_w[((size_t)(mat*E + ebase + i))*E + d];
    }
    int r0 = blockIdx.x*60;
    for (int k = le; k < 60*32; k += 272)
        fs[k] = g_feat[(size_t)r0*D + k];
    __syncthreads();
    float w[32];
    #pragma unroll
    for (int d = 0; d < 32; d++) w[d] = Ws[le*33 + d];
    float* dst = (mat == 0 ? g_qf : g_kf);
    #pragma unroll 2
    for (int rr = 0; rr < 60; rr++){
        float acc = 0.f;
        #pragma unroll
        for (int d = 0; d < 32; d++) acc = fmaf(fs[rr*32 + d], w[d], acc);
        dst[(size_t)(r0 + rr)*E + ebase + le] = acc;
    }
}

// -------- coalesced weight transposes (32x32 smem tiles, z = matrix) --------
__global__ void k_prepT(const float* __restrict__ in_w, const float* __restrict__ Wih,
                        const float* __restrict__ Whh, const float* __restrict__ W2){
    __shared__ float tile[32][33];
    int zz = blockIdx.z;
    int c0 = blockIdx.x*32, r0 = blockIdx.y*32;
    int tx = threadIdx.x, ty = threadIdx.y;  // 32 x 8
    int R, C, ld, off, dstld;
    const float* src; float* dst;
    if (zz == 0){ R = E;   C = U;   src = in_w; ld = E;   off = D; dst = g_WqaT;           dstld = E;   }
    else if (zz == 1){ R = R4U; C = E; src = Wih; ld = E; off = 0; dst = g_Wcat;           dstld = R4U; }
    else if (zz == 2){ R = R4U; C = U; src = Whh; ld = U; off = 0; dst = g_Wcat + (size_t)E*R4U; dstld = R4U; }
    else { R = VOC; C = 256; src = W2;  ld = 256; off = 0; dst = g_W2T;                    dstld = VOCP; }
    if (r0 >= R || c0 >= C) return;
    for (int i = ty; i < 32; i += 8){
        int r = r0 + i, c = c0 + tx;
        if (r < R && c < C) tile[i][tx] = src[(size_t)r*ld + off + c];
    }
    __syncthreads();
    for (int i = ty; i < 32; i += 8){
        int c = c0 + i, r = r0 + tx;
        if (c < C && r < R) dst[(size_t)c*dstld + r] = tile[tx][i];
    }
}

// -------- small prep: bias sum, a/c init, W2T pad-zero ----------------------
__global__ void k_prepS(const float* __restrict__ bih, const float* __restrict__ bhh,
                        const float* __restrict__ a0, const float* __restrict__ c0){
    int i = blockIdx.x*256 + threadIdx.x;
    if (i < R4U) g_bias[i] = bih[i] + bhh[i];
    if (i < BS*U){ g_ab[i] = a0[i]; g_c[i] = c0[i]; }
    if (i < 256*(VOCP-VOC)){
        int k = i / (VOCP-VOC), v = VOC + (i - k*(VOCP-VOC));
        g_W2T[(size_t)k*VOCP + v] = 0.f;
    }
}

// -- A-GEMM on tensor cores (wmma) + exp epilogue -> fp16 E ------------------
__global__ void k_aexp(){
    int bh = blockIdx.z; int b = bh >> 3, h = bh & 7;
    int i0 = blockIdx.y << 6, j0 = blockIdx.x << 6;
    __shared__ __half Qh[64*80];       // [ii][d], d padded 68->80
    __shared__ __half Kh[64*80];       // [jj][d]
    __shared__ float  Cs[64*72];       // fp32 accum tile, ld=72
    int tid = threadIdx.x;             // 256
    int warp = tid >> 5;
    const float* qbase = g_qf + (size_t)(b*G)*E + h*HD;
    const float* kbase = g_kf + (size_t)(b*G)*E + h*HD;
    for (int k = tid; k < 64*80; k += 256){
        int ii = k / 80, d = k - ii*80;
        int gi = i0 + ii, gj = j0 + ii;
        float q = (gi < G && d < HD) ? qbase[(size_t)gi*E + d] : 0.f;
        float kk = (gj < G && d < HD) ? kbase[(size_t)gj*E + d] : 0.f;
        Qh[k] = __float2half(q);
        Kh[k] = __float2half(kk);
    }
    __syncthreads();
    // 16 output tiles (4x4 of 16x16); each of 8 warps does 2
    #pragma unroll
    for (int s = 0; s < 2; s++){
        int tt = warp*2 + s;
        int rt = tt >> 2, ct = tt & 3;
        wmma::fragment<wmma::accumulator, 16,16,16, float> c;
        wmma::fill_fragment(c, 0.f);
        #pragma unroll
        for (int kk = 0; kk < 5; kk++){
            wmma::fragment<wmma::matrix_a, 16,16,16, __half, wmma::row_major> a;
            wmma::fragment<wmma::matrix_b, 16,16,16, __half, wmma::col_major> bf;
            wmma::load_matrix_sync(a,  Qh + rt*16*80 + kk*16, 80);
            wmma::load_matrix_sync(bf, Kh + ct*16*80 + kk*16, 80);
            wmma::mma_sync(c, a, bf, c);
        }
        wmma::store_matrix_sync(Cs + rt*16*72 + ct*16, c, 72, wmma::mem_row_major);
    }
    __syncthreads();
    // epilogue: exp + half2 store
    for (int k = tid; k < 64*32; k += 256){
        int ii = k >> 5, jp = k & 31;
        int i = i0 + ii, j = j0 + jp*2;
        if (i >= G) continue;
        float a0 = Cs[ii*72 + jp*2];
        float a1 = Cs[ii*72 + jp*2 + 1];
        __half* row = g_Ebuf + ((size_t)bh*G + i)*G;
        if (j + 1 < G){
            *(__half2*)(row + j) = __floats2half2_rn(fexp_(a0*INV_S), fexp_(a1*INV_S));
        } else if (j < G){
            row[j] = __float2half(fexp_(a0*INV_S));
        }
    }
}

// ---- per-step attention: qa + e + E-pass + per-head partial ctx -----------
__global__ void k_att(const float* __restrict__ in_b, int par){
    int bh = blockIdx.x; int b = bh >> 3, h = bh & 7;
    int tid = threadIdx.x;               // 384
    int warp = tid >> 5, lane = tid & 31;
    __shared__ float as_[U];
    __shared__ float qp[4][HD];
    __shared__ float qs[HD];
    __shared__ float es[G];
    __shared__ float wp_s[G];
    __shared__ float colsum[12][G];
    const float* ga = g_ab + (size_t)par*BS*U;
    for (int u = tid; u < U; u += 384) as_[u] = ga[b*U + u];
    __syncthreads();
    if (tid < 272){
        int d = tid % HD, part = tid / HD;
        const float* wcol = g_WqaT + h*HD + d;
        float acc = 0.f;
        int u0 = part*128;
        #pragma unroll 8
        for (int u = 0; u < 128; u++) acc = fmaf(as_[u0+u], wcol[(size_t)(u0+u)*E], acc);
        qp[part][d] = acc;
    }
    __syncthreads();
    if (tid < HD) qs[tid] = qp[0][tid]+qp[1][tid]+qp[2][tid]+qp[3][tid] + in_b[h*HD + tid];
    __syncthreads();
    for (int jr = warp; jr < G; jr += 12){
        const float* kfr = g_kf + ((size_t)(b*G + jr))*E + h*HD;
        float p = kfr[lane]*qs[lane] + kfr[lane+32]*qs[lane+32];
        if (lane < 4) p = fmaf(kfr[64+lane], qs[64+lane], p);
        #pragma unroll
        for (int o=16;o;o>>=1) p += __shfl_xor_sync(0xffffffffu, p, o);
        if (lane == 0) es[jr] = fexp_(p * INV_S);
    }
    __syncthreads();
    float racc[12];
    #pragma unroll
    for (int k = 0; k < 12; k++) racc[k] = 0.f;
    const __half2* Eb = (const __half2*)(g_Ebuf + (size_t)bh*G*G);
    const float2* es2 = (const float2*)es;
    for (int i = warp*2; i < G; i += 24){
        const __half2* r0p = Eb + (size_t)i*(G/2);
        const __half2* r1p = r0p + (G/2);
        float2 f0[6], f1[6];
        float d0 = 0.f, d1 = 0.f;
        #pragma unroll
        for (int s = 0; s < 6; s++){
            int jj = lane + 32*s;
            if (jj < G/2){
                f0[s] = __half22float2(r0p[jj]);
                f1[s] = __half22float2(r1p[jj]);
                float2 e2 = es2[jj];
                d0 = fmaf(f0[s].x, e2.x, d0);
                d0 = fmaf(f0[s].y, e2.y, d0);
                d1 = fmaf(f1[s].x, e2.x, d1);
                d1 = fmaf(f1[s].y, e2.y, d1);
            } else {
                f0[s].x = 0.f; f0[s].y = 0.f;
                f1[s].x = 0.f; f1[s].y = 0.f;
            }
        }
        #pragma unroll
        for (int o=16;o;o>>=1){
            d0 += __shfl_xor_sync(0xffffffffu, d0, o);
            d1 += __shfl_xor_sync(0xffffffffu, d1, o);
        }
        float rinv0 = 1.f/d0, rinv1 = 1.f/d1;
        #pragma unroll
        for (int s = 0; s < 6; s++){
            racc[2*s]   = fmaf(f0[s].x, rinv0, fmaf(f1[s].x, rinv1, racc[2*s]));
            racc[2*s+1] = fmaf(f0[s].y, rinv0, fmaf(f1[s].y, rinv1, racc[2*s+1]));
        }
    }
    #pragma unroll
    for (int s = 0; s < 6; s++){
        int jj = lane + 32*s;
        if (jj < G/2){
            colsum[warp][2*jj]   = racc[2*s];
            colsum[warp][2*jj+1] = racc[2*s+1];
        }
    }
    __syncthreads();
    if (tid < G){
        float tot = 0.f;
        #pragma unroll
        for (int w = 0; w < 12; w++) tot += colsum[w][tid];
        float wv = es[tid]*tot;
        wp_s[tid] = wv;
        g_wpart[bh*G + tid] = wv;
    }
    __syncthreads();
    {
        int j0 = warp*30;
        const float* fp = g_feat + ((size_t)b*G + j0)*D + lane;
        float acc = 0.f;
        #pragma unroll 5
        for (int j = 0; j < 30; j++) acc = fmaf(wp_s[j0 + j], fp[(size_t)j*D], acc);
        colsum[warp][lane] = acc;
    }
    __syncthreads();
    if (tid < D){
        float s = 0.f;
        #pragma unroll
        for (int k = 0; k < 12; k++) s += colsum[k][tid];
        g_ctxp[bh*D + tid] = s;
    }
}

// ---- per-step: gate GEMM + (z=0) w-scores out + ctx-from-partials ----------
__global__ void k_gates(const int* __restrict__ text, const float* __restrict__ emb,
                        float* __restrict__ out, int t, int par){
    int z  = blockIdx.z;
    int b0 = blockIdx.y*8;
    int tid = threadIdx.x;               // 128
    int r = blockIdx.x*128 + tid;        // grid.x = 16
    __shared__ float xs[8][XH];
    int x0 = z*XH;
    const float* ga = g_ab + (size_t)par*BS*U;
    if (z == 0){
        if (blockIdx.x == 0){
            for (int idx = tid; idx < 8*G; idx += 128){
                int bb = idx / G, j = idx - bb*G;
                const float* p = g_wpart + (size_t)(b0+bb)*H*G + j;
                float acc = 0.f;
                #pragma unroll
                for (int hh = 0; hh < H; hh++) acc += p[hh*G];
                out[(size_t)BS*T*VOC + ((size_t)(b0+bb)*T + t)*G + j] = acc * (1.f/(float)(H*G));
            }
        }
        for (int pr = tid; pr < 256; pr += 128){
            int bb = pr >> 5, d = pr & 31;
            const float* cp = g_ctxp + (size_t)(b0+bb)*H*D + d;
            float acc = 0.f;
            #pragma unroll
            for (int hh = 0; hh < H; hh++) acc += cp[hh*D];
            xs[bb][d] = acc * (1.f/(float)(H*G));
        }
        for (int bb = 0; bb < 8; bb++){
            int b = b0 + bb;
            int tok = text[b*T + t];
            for (int xx = tid; xx < XH; xx += 128){
                if (xx >= D) xs[bb][xx] = emb[(size_t)tok*TD + (xx - D)];
            }
        }
    } else {
        for (int bb = 0; bb < 8; bb++){
            int b = b0 + bb;
            int tok = text[b*T + t];
            for (int xx = tid; xx < XH; xx += 128){
                int x = x0 + xx;
                xs[bb][xx] = (x < E) ? emb[(size_t)tok*TD + (x - D)] : ga[b*U + (x - E)];
            }
        }
    }
    __syncthreads();
    float acc[8] = {};
    const float* wp = g_Wcat + (size_t)x0*R4U + r;
    #pragma unroll 4
    for (int xx = 0; xx < XH; xx++){
        float w = wp[(size_t)xx*R4U];
        #pragma unroll
        for (int bb = 0; bb < 8; bb++) acc[bb] = fmaf(xs[bb][xx], w, acc[bb]);
    }
    float* dst = (z == 0) ? g_gates : g_gates2;
    #pragma unroll
    for (int bb = 0; bb < 8; bb++) dst[(size_t)(b0+bb)*R4U + r] = acc[bb];
}

// ------------- per-step LSTM cell + LN (small; on critical path) -----------
__global__ void k_lstm(const float* __restrict__ ln_g, const float* __restrict__ ln_b,
                       int outpar){
    int b = blockIdx.x, tid = threadIdx.x;   // 512
    __shared__ float r1[16], r2[16];
    int u = tid;
    const float* gr0 = g_gates  + (size_t)b*R4U;
    const float* gr1 = g_gates2 + (size_t)b*R4U;
    float gi = gr0[u]       + gr1[u]       + g_bias[u];
    float gf = gr0[U+u]     + gr1[U+u]     + g_bias[U+u];
    float gg = gr0[2*U+u]   + gr1[2*U+u]   + g_bias[2*U+u];
    float go = gr0[3*U+u]   + gr1[3*U+u]   + g_bias[3*U+u];
    float c = sigmoidf_(gf)*g_c[b*U+u] + sigmoidf_(gi)*tanhf(gg);
    g_c[b*U+u] = c;
    float hh = sigmoidf_(go)*tanhf(c);
    float s1 = hh, s2 = hh*hh;
    #pragma unroll
    for (int o=16;o;o>>=1){ s1 += __shfl_xor_sync(0xffffffffu,s1,o); s2 += __shfl_xor_sync(0xffffffffu,s2,o); }
    int w = tid>>5, l = tid&31;
    if (l==0){ r1[w]=s1; r2[w]=s2; }
    __syncthreads();
    if (tid==0){
        float t1=0.f, t2=0.f;
        #pragma unroll
        for (int i=0;i<16;i++){ t1+=r1[i]; t2+=r2[i]; }
        r1[0]=t1; r2[0]=t2;
    }
    __syncthreads();
    float m = r1[0]*(1.f/(float)U);
    float var = r2[0]*(1.f/(float)U) - m*m;
    float a = (hh-m)*rsqrtf(var+1e-5f)*ln_g[u]+ln_b[u];
    g_ab[(size_t)outpar*BS*U + b*U + u] = a;
}

// ------------- per-step MLP layer 1 (on stream B) ---------------------------
__global__ void k_mlp1(const float* __restrict__ W1, const float* __restrict__ b1, int par){
    int b = blockIdx.x, tid = threadIdx.x;   // 512
    __shared__ float sact[U];
    sact[tid] = leakyf_(g_ab[(size_t)par*BS*U + b*U + tid]);
    __syncthreads();
    int w = tid>>5, l = tid&31;
    #pragma unroll
    for (int kk = 0; kk < 16; kk++){
        int k = w*16 + kk;
        const float* wrow = W1 + (size_t)k*U;
        float acc = 0.f;
        #pragma unroll 4
        for (int uu = l; uu < U; uu += 32) acc = fmaf(sact[uu], wrow[uu], acc);
        #pragma unroll
        for (int o=16;o;o>>=1) acc += __shfl_xor_sync(0xffffffffu, acc, o);
        if (l==0) g_h1[b*256+k] = leakyf_(acc + b1[k]);
    }
}

// ------------- per-step MLP layer 2 (register-blocked GEMM) ----------------
__global__ void k_mlp2(const float* __restrict__ b2){
    int v0 = blockIdx.x*64;
    int b0 = blockIdx.y*32;
    int tid = threadIdx.x;                   // 256
    int tx = tid & 31, ty = tid >> 5;
    __shared__ float h1T[256*36];
    for (int i = tid; i < 256*32; i += 256){
        int k = i & 255, bb = i >> 8;
        h1T[k*36 + bb] = g_h1[(size_t)(b0+bb)*256 + k];
    }
    __syncthreads();
    int v = v0 + tx*2;
    float acc[2][4] = {};
    const float* w2 = g_W2T + v;
    const float* hp = h1T + ty*4;
    #pragma unroll 4
    for (int k = 0; k < 256; k++){
        float2 w = *(const float2*)(w2 + (size_t)k*VOCP);
        float4 hv = *(const float4*)(hp + k*36);
        acc[0][0] = fmaf(w.x, hv.x, acc[0][0]);
        acc[0][1] = fmaf(w.x, hv.y, acc[0][1]);
        acc[0][2] = fmaf(w.x, hv.z, acc[0][2]);
        acc[0][3] = fmaf(w.x, hv.w, acc[0][3]);
        acc[1][0] = fmaf(w.y, hv.x, acc[1][0]);
        acc[1][1] = fmaf(w.y, hv.y, acc[1][1]);
        acc[1][2] = fmaf(w.y, hv.z, acc[1][2]);
        acc[1][3] = fmaf(w.y, hv.w, acc[1][3]);
    }
    float bv0 = (v < VOC)   ? b2[v]   : 0.f;
    float bv1 = (v+1 < VOC) ? b2[v+1] : 0.f;
    #pragma unroll
    for (int bb = 0; bb < 4; bb++){
        int b = b0 + ty*4 + bb;
        if (v < VOC)   g_logits[(size_t)b*VOC + v]   = acc[0][bb] + bv0;
        if (v+1 < VOC) g_logits[(size_t)b*VOC + v+1] = acc[1][bb] + bv1;
    }
}

// ------------- per-step softmax over VOC -----------------------------------
__global__ void k_soft(float* __restrict__ out, int t){
    int b = blockIdx.x, tid = threadIdx.x;   // 512
    __shared__ float buf[VOC];
    __shared__ float red[16];
    float m = -1e30f;
    for (int v = tid; v < VOC; v += 512){
        float x = g_logits[(size_t)b*VOC+v];
        buf[v] = x;
        m = fmaxf(m, x);
    }
    #pragma unroll
    for (int o=16;o;o>>=1) m = fmaxf(m, __shfl_xor_sync(0xffffffffu,m,o));
    if ((tid&31)==0) red[tid>>5]=m;
    __syncthreads();
    if (tid==0){ float mm=red[0]; for(int i=1;i<16;i++) mm=fmaxf(mm,red[i]); red[0]=mm; }
    __syncthreads();
    m = red[0];
    __syncthreads();
    float s = 0.f;
    for (int v = tid; v < VOC; v += 512){
        float e = fexp_(buf[v]-m);
        buf[v] = e;
        s += e;
    }
    #pragma unroll
    for (int o=16;o;o>>=1) s += __shfl_xor_sync(0xffffffffu,s,o);
    if ((tid&31)==0) red[tid>>5]=s;
    __syncthreads();
    if (tid==0){ float ss=0.f; for(int i=0;i<16;i++) ss+=red[i]; red[0]=1.f/ss; }
    __syncthreads();
    float inv = red[0];
    float* orow = out + ((size_t)b*T + t)*VOC;
    for (int v = tid; v < VOC; v += 512) orow[v] = buf[v]*inv;
}

// ---------------------------------------------------------------------------
extern "C" void kernel_launch(void* const* d_in, const int* in_sizes, int n_in,
                              void* d_out, int out_size){
    const float* features = (const float*)d_in[0];
    const int*   text     = (const int*)  d_in[1];
    const float* a0       = (const float*)d_in[2];
    const float* c0       = (const float*)d_in[3];
    const float* enc_W    = (const float*)d_in[4];
    const float* enc_b    = (const float*)d_in[5];
    const float* enc_g    = (const float*)d_in[6];
    const float* enc_beta = (const float*)d_in[7];
    const float* emb      = (const float*)d_in[8];
    const float* in_w     = (const float*)d_in[9];
    const float* in_b     = (const float*)d_in[10];
    const float* Wih      = (const float*)d_in[11];
    const float* Whh      = (const float*)d_in[12];
    const float* bih      = (const float*)d_in[13];
    const float* bhh      = (const float*)d_in[14];
    const float* ln_g     = (const float*)d_in[15];
    const float* ln_b     = (const float*)d_in[16];
    const float* W1       = (const float*)d_in[17];
    const float* b1       = (const float*)d_in[18];
    const float* W2       = (const float*)d_in[19];
    const float* b2       = (const float*)d_in[20];
    float* out = (float*)d_out;
    (void)in_sizes; (void)n_in; (void)out_size;

    cudaStream_t s0 = 0, sB;
    cudaStreamCreateWithFlags(&sB, cudaStreamNonBlocking);
    cudaEvent_t evF, evP, evL, evE, evQ0, evQ1;
    cudaEventCreateWithFlags(&evF, cudaEventDisableTiming);
    cudaEventCreateWithFlags(&evP, cudaEventDisableTiming);
    cudaEventCreateWithFlags(&evL, cudaEventDisableTiming);
    cudaEventCreateWithFlags(&evE, cudaEventDisableTiming);
    cudaEventCreateWithFlags(&evQ0, cudaEventDisableTiming);
    cudaEventCreateWithFlags(&evQ1, cudaEventDisableTiming);

    cudaEventRecord(evF, s0);
    cudaStreamWaitEvent(sB, evF, 0);

    k_encoder<<<G, 256, 0, s0>>>(features, enc_W, enc_b, enc_g, enc_beta);   // 0
    k_qkf<<<dim3(BS*G/60, 4), 272, 0, s0>>>(in_w);                           // 1
    k_prepT<<<dim3(17, 157, 4), dim3(32, 8), 0, sB>>>(in_w, Wih, Whh, W2);   // 2
    k_aexp<<<dim3(6, 6, BS*H), 256, 0, s0>>>();                              // 3 (profiled)
    k_prepS<<<(BS*U + 255)/256, 256, 0, sB>>>(bih, bhh, a0, c0);             // 4
    cudaEventRecord(evP, sB);
    cudaStreamWaitEvent(s0, evP, 0);

    for (int t = 0; t < T; t++){
        int par = t & 1, npar = (t + 1) & 1;
        k_att  <<<BS*H, 384, 0, s0>>>(in_b, par);
        k_gates<<<dim3(16, 8, 2), 128, 0, s0>>>(text, emb, out, t, par);
        // WAR: lstm(t) writes a-buffer npar, read by mlp1(t-2) (same parity)
        if (t >= 2) cudaStreamWaitEvent(s0, (par == 0) ? evQ0 : evQ1, 0);
        k_lstm <<<BS, 512, 0, s0>>>(ln_g, ln_b, npar);
        cudaEventRecord(evL, s0);
        cudaStreamWaitEvent(sB, evL, 0);
        k_mlp1<<<BS, 512, 0, sB>>>(W1, b1, npar);
        cudaEventRecord((par == 0) ? evQ0 : evQ1, sB);
        k_mlp2<<<dim3((VOC+63)/64, 2), 256, 0, sB>>>(b2);
        k_soft<<<BS, 512, 0, sB>>>(out, t);
    }
    cudaEventRecord(evE, sB);
    cudaStreamWaitEvent(s0, evE, 0);
}

// round 15
// speedup vs baseline: 1.1759x; 1.0632x over previous
#include <cuda_runtime.h>
#include <cuda_fp16.h>

#define BS 64
#define G 360
#define V 100
#define D 32
#define U 512
#define T 15
#define VOC 5000
#define VOCP 5120
#define TD 512
#define H 8
#define E 544          // D + U
#define HD 68          // E / H
#define NEG 0.2f
#define INV_S 0.12126781251816648f   // 1/sqrt(68)
#define XDIM 1056      // E + U
#define XH 528         // XDIM/2 (split-K half)
#define R4U 2048       // 4*U

// ----------------------------- device scratch -----------------------------
__device__ float  g_feat[BS*G*D];
__device__ float  g_qf[(size_t)BS*G*E];
__device__ float  g_kf[(size_t)BS*G*E];
__device__ __half g_Ebuf[(size_t)BS*H*G*G];   // fp16 exp(A), shift-free
__device__ float  g_WqaT[U*E];
__device__ float  g_Wcat[(size_t)XDIM*R4U];
__device__ float  g_bias[R4U];
__device__ float  g_W2T[256*VOCP];            // fp32 W2^T, padded tail zeroed
__device__ float  g_wpart[BS*H*G];
__device__ float  g_ctxp[BS*H*D];             // per-head partial ctx
__device__ float  g_gates[BS*R4U];
__device__ float  g_gates2[BS*R4U];
__device__ float  g_ab[2*BS*U];               // double-buffered hidden state a
__device__ float  g_cb[2*BS*U];               // double-buffered cell state c
__device__ float  g_h1[BS*256];
__device__ float  g_logits[BS*VOC];

__device__ __forceinline__ float sigmoidf_(float x){ return 1.f/(1.f+__expf(-x)); }
__device__ __forceinline__ float leakyf_(float x){ return x > 0.f ? x : NEG*x; }

__device__ __forceinline__ float fexp_(float x){
    float t = x * 1.4426950408889634f;
    float r = rintf(t);
    float f = t - r;
    float p =          1.3333558e-3f;
    p = fmaf(p, f, 9.6181291e-3f);
    p = fmaf(p, f, 5.5504109e-2f);
    p = fmaf(p, f, 2.4022651e-1f);
    p = fmaf(p, f, 6.9314718e-1f);
    p = fmaf(p, f, 1.0f);
    int ei = (int)r;
    if (ei < -126) ei = -126;
    return p * __int_as_float((ei + 127) << 23);
}

// ---------------------- encoder: feat = lrelu(LN(x@W+b)) -------------------
__global__ void k_encoder(const float* __restrict__ features, const float* __restrict__ enc_W,
                          const float* __restrict__ enc_b, const float* __restrict__ enc_g,
                          const float* __restrict__ enc_beta){
    int g = blockIdx.x;
    int tid = threadIdx.x;               // 256
    int warp = tid >> 5, lane = tid & 31;
    __shared__ float Ws[D*101];
    __shared__ float bs_[D];
    __shared__ float xw[8][V];
    for (int k = tid; k < D*V; k += 256){
        int d = k / V, v = k - d*V;
        Ws[d*101 + v] = enc_W[(size_t)g*D*V + k];
    }
    if (tid < D) bs_[tid] = enc_b[g*D + tid];
    __syncthreads();
    float gg = enc_g[lane], bb = enc_beta[lane];
    for (int b = warp; b < BS; b += 8){
        for (int v = lane; v < V; v += 32) xw[warp][v] = features[((size_t)b*G + g)*V + v];
        __syncwarp();
        const float* w = Ws + lane*101;
        float acc = bs_[lane];
        #pragma unroll 4
        for (int v = 0; v < V; v++) acc = fmaf(xw[warp][v], w[v], acc);
        float m = acc;
        #pragma unroll
        for (int o=16;o;o>>=1) m += __shfl_xor_sync(0xffffffffu, m, o);
        m *= (1.f/32.f);
        float dv = acc - m, vv = dv*dv;
        #pragma unroll
        for (int o=16;o;o>>=1) vv += __shfl_xor_sync(0xffffffffu, vv, o);
        vv *= (1.f/32.f);
        float y = dv*rsqrtf(vv+1e-5f)*gg + bb;
        g_feat[((size_t)b*G + g)*D + lane] = leakyf_(y);
        __syncwarp();
    }
}

// ---------------- qf / kf projections (weights in registers) ---------------
__global__ void k_qkf(const float* __restrict__ in_w){
    int mat = blockIdx.y >> 1;
    int eh  = blockIdx.y & 1;
    int le  = threadIdx.x;               // 0..271
    int ebase = eh*272;
    __shared__ float Ws[272*33];
    __shared__ float fs[60*32];
    for (int k = le; k < 272*32; k += 272){
        int i = k >> 5, d = k & 31;
        Ws[i*33 + d] = in_w[((size_t)(mat*E + ebase + i))*E + d];
    }
    int r0 = blockIdx.x*60;
    for (int k = le; k < 60*32; k += 272)
        fs[k] = g_feat[(size_t)r0*D + k];
    __syncthreads();
    float w[32];
    #pragma unroll
    for (int d = 0; d < 32; d++) w[d] = Ws[le*33 + d];
    float* dst = (mat == 0 ? g_qf : g_kf);
    #pragma unroll 2
    for (int rr = 0; rr < 60; rr++){
        float acc = 0.f;
        #pragma unroll
        for (int d = 0; d < 32; d++) acc = fmaf(fs[rr*32 + d], w[d], acc);
        dst[(size_t)(r0 + rr)*E + ebase + le] = acc;
    }
}

// -------- coalesced weight transposes (32x32 smem tiles, z = matrix) --------
__global__ void k_prepT(const float* __restrict__ in_w, const float* __restrict__ Wih,
                        const float* __restrict__ Whh, const float* __restrict__ W2){
    __shared__ float tile[32][33];
    int zz = blockIdx.z;
    int c0 = blockIdx.x*32, r0 = blockIdx.y*32;
    int tx = threadIdx.x, ty = threadIdx.y;  // 32 x 8
    int R, C, ld, off, dstld;
    const float* src; float* dst;
    if (zz == 0){ R = E;   C = U;   src = in_w; ld = E;   off = D; dst = g_WqaT;           dstld = E;   }
    else if (zz == 1){ R = R4U; C = E; src = Wih; ld = E; off = 0; dst = g_Wcat;           dstld = R4U; }
    else if (zz == 2){ R = R4U; C = U; src = Whh; ld = U; off = 0; dst = g_Wcat + (size_t)E*R4U; dstld = R4U; }
    else { R = VOC; C = 256; src = W2;  ld = 256; off = 0; dst = g_W2T;                    dstld = VOCP; }
    if (r0 >= R || c0 >= C) return;
    for (int i = ty; i < 32; i += 8){
        int r = r0 + i, c = c0 + tx;
        if (r < R && c < C) tile[i][tx] = src[(size_t)r*ld + off + c];
    }
    __syncthreads();
    for (int i = ty; i < 32; i += 8){
        int c = c0 + i, r = r0 + tx;
        if (c < C && r < R) dst[(size_t)c*dstld + r] = tile[tx][i];
    }
}

// -------- small prep: bias sum, a/c init, W2T pad-zero ----------------------
__global__ void k_prepS(const float* __restrict__ bih, const float* __restrict__ bhh,
                        const float* __restrict__ a0, const float* __restrict__ c0){
    int i = blockIdx.x*256 + threadIdx.x;
    if (i < R4U) g_bias[i] = bih[i] + bhh[i];
    if (i < BS*U){ g_ab[i] = a0[i]; g_cb[i] = c0[i]; }
    if (i < 256*(VOCP-VOC)){
        int k = i / (VOCP-VOC), v = VOC + (i - k*(VOCP-VOC));
        g_W2T[(size_t)k*VOCP + v] = 0.f;
    }
}

// -- A-GEMM (HFMA2) with exp epilogue: E[b,h,i,j] = exp(qf.kf/sqrt(HD)) fp16 -
__global__ void k_aexp(){
    int bh = blockIdx.z; int b = bh >> 3, h = bh & 7;
    int i0 = blockIdx.y << 6, j0 = blockIdx.x << 6;
    __shared__ __half2 Qs[34*68];
    __shared__ __half2 Ks[34*68];
    int tid = threadIdx.x;             // 256
    const float* qbase = g_qf + (size_t)(b*G)*E + h*HD;
    for (int k = tid; k < 64*34; k += 256){
        int ii = k / 34, dp = k - ii*34;
        int gi = i0 + ii;
        float x0 = 0.f, x1 = 0.f;
        if (gi < G){
            x0 = qbase[(size_t)gi*E + 2*dp];
            x1 = qbase[(size_t)gi*E + 2*dp + 1];
        }
        Qs[dp*68 + ii] = __floats2half2_rn(x0, x1);
    }
    const float* kbase = g_kf + (size_t)(b*G)*E + h*HD;
    for (int k = tid; k < 64*34; k += 256){
        int jj = k / 34, dp = k - jj*34;
        int gj = j0 + jj;
        float x0 = 0.f, x1 = 0.f;
        if (gj < G){
            x0 = kbase[(size_t)gj*E + 2*dp];
            x1 = kbase[(size_t)gj*E + 2*dp + 1];
        }
        Ks[dp*68 + jj] = __floats2half2_rn(x0, x1);
    }
    __syncthreads();
    int tx = tid & 15, ty = tid >> 4;
    __half2 acc[4][4];
    #pragma unroll
    for (int r = 0; r < 4; r++)
        #pragma unroll
        for (int c = 0; c < 4; c++) acc[r][c] = __floats2half2_rn(0.f, 0.f);
    #pragma unroll 2
    for (int dp = 0; dp < 34; dp++){
        float4 qv = *(const float4*)&Qs[dp*68 + (ty<<2)];
        float4 kv = *(const float4*)&Ks[dp*68 + (tx<<2)];
        __half2 q2[4], k2[4];
        q2[0] = *(__half2*)&qv.x; q2[1] = *(__half2*)&qv.y;
        q2[2] = *(__half2*)&qv.z; q2[3] = *(__half2*)&qv.w;
        k2[0] = *(__half2*)&kv.x; k2[1] = *(__half2*)&kv.y;
        k2[2] = *(__half2*)&kv.z; k2[3] = *(__half2*)&kv.w;
        #pragma unroll
        for (int r = 0; r < 4; r++)
            #pragma unroll
            for (int c = 0; c < 4; c++) acc[r][c] = __hfma2(q2[r], k2[c], acc[r][c]);
    }
    #pragma unroll
    for (int r = 0; r < 4; r++){
        int i = i0 + (ty<<2) + r;
        if (i >= G) continue;
        __half* row = g_Ebuf + ((size_t)bh*G + i)*G;
        #pragma unroll
        for (int c = 0; c < 4; c += 2){
            int j = j0 + (tx<<2) + c;
            float a0v = __low2float(acc[r][c])   + __high2float(acc[r][c]);
            float a1v = __low2float(acc[r][c+1]) + __high2float(acc[r][c+1]);
            if (j + 1 < G){
                *(__half2*)(row + j) = __floats2half2_rn(fexp_(a0v*INV_S), fexp_(a1v*INV_S));
            } else if (j < G){
                row[j] = __float2half(fexp_(a0v*INV_S));
            }
        }
    }
}

// == fused per-step kernel: [lstm(t-1) if t>0] + qa + e + E-pass + ctxp ======
// All 8 bh-blocks of a given b compute the lstm phase redundantly with
// identical fp32 ops -> identical (deterministic) global writes.
__global__ void k_attF(const float* __restrict__ in_b, const float* __restrict__ ln_g,
                       const float* __restrict__ ln_bv, int t){
    int bh = blockIdx.x; int b = bh >> 3, h = bh & 7;
    int tid = threadIdx.x;               // 384
    int warp = tid >> 5, lane = tid & 31;
    __shared__ float as_[U];
    __shared__ float qp[4][HD];
    __shared__ float qs[HD];
    __shared__ float es[G];
    __shared__ float wp_s[G];
    __shared__ float colsum[12][G];
    __shared__ float r1[12], r2[12];
    int par = t & 1;
    if (t == 0){
        for (int u = tid; u < U; u += 384) as_[u] = g_ab[b*U + u];
        __syncthreads();
    } else {
        // --- lstm(t-1): gates -> c[par], a[par] (redundant per-b) ---
        int cin = (t - 1) & 1;
        const float* gr0 = g_gates  + (size_t)b*R4U;
        const float* gr1 = g_gates2 + (size_t)b*R4U;
        float hhv[2]; int nown = (tid < 128) ? 2 : 1;
        float s1 = 0.f, s2 = 0.f;
        #pragma unroll
        for (int k = 0; k < 2; k++){
            if (k < nown){
                int u = tid + k*384;
                float gi = gr0[u]       + gr1[u]       + g_bias[u];
                float gf = gr0[U+u]     + gr1[U+u]     + g_bias[U+u];
                float gg = gr0[2*U+u]   + gr1[2*U+u]   + g_bias[2*U+u];
                float go = gr0[3*U+u]   + gr1[3*U+u]   + g_bias[3*U+u];
                float c = sigmoidf_(gf)*g_cb[(size_t)cin*BS*U + b*U + u] + sigmoidf_(gi)*tanhf(gg);
                g_cb[(size_t)par*BS*U + b*U + u] = c;
                float hh = sigmoidf_(go)*tanhf(c);
                hhv[k] = hh;
                s1 += hh; s2 += hh*hh;
            }
        }
        #pragma unroll
        for (int o=16;o;o>>=1){ s1 += __shfl_xor_sync(0xffffffffu,s1,o); s2 += __shfl_xor_sync(0xffffffffu,s2,o); }
        if (lane == 0){ r1[warp] = s1; r2[warp] = s2; }
        __syncthreads();
        if (tid == 0){
            float t1 = 0.f, t2 = 0.f;
            #pragma unroll
            for (int i = 0; i < 12; i++){ t1 += r1[i]; t2 += r2[i]; }
            r1[0] = t1; r2[0] = t2;
        }
        __syncthreads();
        float m = r1[0]*(1.f/(float)U);
        float var = r2[0]*(1.f/(float)U) - m*m;
        float rstd = rsqrtf(var + 1e-5f);
        #pragma unroll
        for (int k = 0; k < 2; k++){
            if (k < nown){
                int u = tid + k*384;
                float a = (hhv[k] - m)*rstd*ln_g[u] + ln_bv[u];
                as_[u] = a;
                g_ab[(size_t)par*BS*U + b*U + u] = a;
            }
        }
        __syncthreads();
    }
    // --- qa slice (incl. bq) ---
    if (tid < 272){
        int d = tid % HD, part = tid / HD;
        const float* wcol = g_WqaT + h*HD + d;
        float acc = 0.f;
        int u0 = part*128;
        #pragma unroll 8
        for (int u = 0; u < 128; u++) acc = fmaf(as_[u0+u], wcol[(size_t)(u0+u)*E], acc);
        qp[part][d] = acc;
    }
    __syncthreads();
    if (tid < HD) qs[tid] = qp[0][tid]+qp[1][tid]+qp[2][tid]+qp[3][tid] + in_b[h*HD + tid];
    __syncthreads();
    // --- e_j = exp(qa.kf_j / sqrt(HD)) ---
    for (int jr = warp; jr < G; jr += 12){
        const float* kfr = g_kf + ((size_t)(b*G + jr))*E + h*HD;
        float p = kfr[lane]*qs[lane] + kfr[lane+32]*qs[lane+32];
        if (lane < 4) p = fmaf(kfr[64+lane], qs[64+lane], p);
        #pragma unroll
        for (int o=16;o;o>>=1) p += __shfl_xor_sync(0xffffffffu, p, o);
        if (lane == 0) es[jr] = fexp_(p * INV_S);
    }
    __syncthreads();
    // --- streaming pass over E, 2 rows per warp iteration ---
    float racc[12];
    #pragma unroll
    for (int k = 0; k < 12; k++) racc[k] = 0.f;
    const __half2* Eb = (const __half2*)(g_Ebuf + (size_t)bh*G*G);
    const float2* es2 = (const float2*)es;
    for (int i = warp*2; i < G; i += 24){
        const __half2* r0p = Eb + (size_t)i*(G/2);
        const __half2* r1p = r0p + (G/2);
        float2 f0[6], f1[6];
        float d0 = 0.f, d1 = 0.f;
        #pragma unroll
        for (int s = 0; s < 6; s++){
            int jj = lane + 32*s;
            if (jj < G/2){
                f0[s] = __half22float2(r0p[jj]);
                f1[s] = __half22float2(r1p[jj]);
                float2 e2 = es2[jj];
                d0 = fmaf(f0[s].x, e2.x, d0);
                d0 = fmaf(f0[s].y, e2.y, d0);
                d1 = fmaf(f1[s].x, e2.x, d1);
                d1 = fmaf(f1[s].y, e2.y, d1);
            } else {
                f0[s].x = 0.f; f0[s].y = 0.f;
                f1[s].x = 0.f; f1[s].y = 0.f;
            }
        }
        #pragma unroll
        for (int o=16;o;o>>=1){
            d0 += __shfl_xor_sync(0xffffffffu, d0, o);
            d1 += __shfl_xor_sync(0xffffffffu, d1, o);
        }
        float rinv0 = 1.f/d0, rinv1 = 1.f/d1;
        #pragma unroll
        for (int s = 0; s < 6; s++){
            racc[2*s]   = fmaf(f0[s].x, rinv0, fmaf(f1[s].x, rinv1, racc[2*s]));
            racc[2*s+1] = fmaf(f0[s].y, rinv0, fmaf(f1[s].y, rinv1, racc[2*s+1]));
        }
    }
    #pragma unroll
    for (int s = 0; s < 6; s++){
        int jj = lane + 32*s;
        if (jj < G/2){
            colsum[warp][2*jj]   = racc[2*s];
            colsum[warp][2*jj+1] = racc[2*s+1];
        }
    }
    __syncthreads();
    if (tid < G){
        float tot = 0.f;
        #pragma unroll
        for (int w = 0; w < 12; w++) tot += colsum[w][tid];
        float wv = es[tid]*tot;
        wp_s[tid] = wv;
        g_wpart[bh*G + tid] = wv;
    }
    __syncthreads();
    {
        int j0 = warp*30;
        const float* fp = g_feat + ((size_t)b*G + j0)*D + lane;
        float acc = 0.f;
        #pragma unroll 5
        for (int j = 0; j < 30; j++) acc = fmaf(wp_s[j0 + j], fp[(size_t)j*D], acc);
        colsum[warp][lane] = acc;
    }
    __syncthreads();
    if (tid < D){
        float s = 0.f;
        #pragma unroll
        for (int k = 0; k < 12; k++) s += colsum[k][tid];
        g_ctxp[bh*D + tid] = s;
    }
}

// ---- per-step: gate GEMM + (z=0) w-scores out + ctx-from-partials ----------
__global__ void k_gates(const int* __restrict__ text, const float* __restrict__ emb,
                        float* __restrict__ out, int t, int par){
    int z  = blockIdx.z;
    int b0 = blockIdx.y*8;
    int tid = threadIdx.x;               // 128
    int r = blockIdx.x*128 + tid;        // grid.x = 16
    __shared__ float xs[8][XH];
    int x0 = z*XH;
    const float* ga = g_ab + (size_t)par*BS*U;
    if (z == 0){
        if (blockIdx.x == 0){
            for (int idx = tid; idx < 8*G; idx += 128){
                int bb = idx / G, j = idx - bb*G;
                const float* p = g_wpart + (size_t)(b0+bb)*H*G + j;
                float acc = 0.f;
                #pragma unroll
                for (int hh = 0; hh < H; hh++) acc += p[hh*G];
                out[(size_t)BS*T*VOC + ((size_t)(b0+bb)*T + t)*G + j] = acc * (1.f/(float)(H*G));
            }
        }
        for (int pr = tid; pr < 256; pr += 128){
            int bb = pr >> 5, d = pr & 31;
            const float* cp = g_ctxp + (size_t)(b0+bb)*H*D + d;
            float acc = 0.f;
            #pragma unroll
            for (int hh = 0; hh < H; hh++) acc += cp[hh*D];
            xs[bb][d] = acc * (1.f/(float)(H*G));
        }
        for (int bb = 0; bb < 8; bb++){
            int b = b0 + bb;
            int tok = text[b*T + t];
            for (int xx = tid; xx < XH; xx += 128){
                if (xx >= D) xs[bb][xx] = emb[(size_t)tok*TD + (xx - D)];
            }
        }
    } else {
        for (int bb = 0; bb < 8; bb++){
            int b = b0 + bb;
            int tok = text[b*T + t];
            for (int xx = tid; xx < XH; xx += 128){
                int x = x0 + xx;
                xs[bb][xx] = (x < E) ? emb[(size_t)tok*TD + (x - D)] : ga[b*U + (x - E)];
            }
        }
    }
    __syncthreads();
    float acc[8] = {};
    const float* wp = g_Wcat + (size_t)x0*R4U + r;
    #pragma unroll 4
    for (int xx = 0; xx < XH; xx++){
        float w = wp[(size_t)xx*R4U];
        #pragma unroll
        for (int bb = 0; bb < 8; bb++) acc[bb] = fmaf(xs[bb][xx], w, acc[bb]);
    }
    float* dst = (z == 0) ? g_gates : g_gates2;
    #pragma unroll
    for (int bb = 0; bb < 8; bb++) dst[(size_t)(b0+bb)*R4U + r] = acc[bb];
}

// ------------- final LSTM cell + LN (only for t = T-1) ----------------------
__global__ void k_lstmF(const float* __restrict__ ln_g, const float* __restrict__ ln_b,
                        int cin, int outpar){
    int b = blockIdx.x, tid = threadIdx.x;   // 512
    __shared__ float r1[16], r2[16];
    int u = tid;
    const float* gr0 = g_gates  + (size_t)b*R4U;
    const float* gr1 = g_gates2 + (size_t)b*R4U;
    float gi = gr0[u]       + gr1[u]       + g_bias[u];
    float gf = gr0[U+u]     + gr1[U+u]     + g_bias[U+u];
    float gg = gr0[2*U+u]   + gr1[2*U+u]   + g_bias[2*U+u];
    float go = gr0[3*U+u]   + gr1[3*U+u]   + g_bias[3*U+u];
    float c = sigmoidf_(gf)*g_cb[(size_t)cin*BS*U + b*U + u] + sigmoidf_(gi)*tanhf(gg);
    g_cb[(size_t)outpar*BS*U + b*U + u] = c;
    float hh = sigmoidf_(go)*tanhf(c);
    float s1 = hh, s2 = hh*hh;
    #pragma unroll
    for (int o=16;o;o>>=1){ s1 += __shfl_xor_sync(0xffffffffu,s1,o); s2 += __shfl_xor_sync(0xffffffffu,s2,o); }
    int w = tid>>5, l = tid&31;
    if (l==0){ r1[w]=s1; r2[w]=s2; }
    __syncthreads();
    if (tid==0){
        float t1=0.f, t2=0.f;
        #pragma unroll
        for (int i=0;i<16;i++){ t1+=r1[i]; t2+=r2[i]; }
        r1[0]=t1; r2[0]=t2;
    }
    __syncthreads();
    float m = r1[0]*(1.f/(float)U);
    float var = r2[0]*(1.f/(float)U) - m*m;
    float a = (hh-m)*rsqrtf(var+1e-5f)*ln_g[u]+ln_b[u];
    g_ab[(size_t)outpar*BS*U + b*U + u] = a;
}

// ------------- per-step MLP layer 1 (on stream B) ---------------------------
__global__ void k_mlp1(const float* __restrict__ W1, const float* __restrict__ b1, int par){
    int b = blockIdx.x, tid = threadIdx.x;   // 512
    __shared__ float sact[U];
    sact[tid] = leakyf_(g_ab[(size_t)par*BS*U + b*U + tid]);
    __syncthreads();
    int w = tid>>5, l = tid&31;
    #pragma unroll
    for (int kk = 0; kk < 16; kk++){
        int k = w*16 + kk;
        const float* wrow = W1 + (size_t)k*U;
        float acc = 0.f;
        #pragma unroll 4
        for (int uu = l; uu < U; uu += 32) acc = fmaf(sact[uu], wrow[uu], acc);
        #pragma unroll
        for (int o=16;o;o>>=1) acc += __shfl_xor_sync(0xffffffffu, acc, o);
        if (l==0) g_h1[b*256+k] = leakyf_(acc + b1[k]);
    }
}

// ------------- per-step MLP layer 2 (register-blocked GEMM) ----------------
__global__ void k_mlp2(const float* __restrict__ b2){
    int v0 = blockIdx.x*64;
    int b0 = blockIdx.y*32;
    int tid = threadIdx.x;                   // 256
    int tx = tid & 31, ty = tid >> 5;
    __shared__ float h1T[256*36];
    for (int i = tid; i < 256*32; i += 256){
        int k = i & 255, bb = i >> 8;
        h1T[k*36 + bb] = g_h1[(size_t)(b0+bb)*256 + k];
    }
    __syncthreads();
    int v = v0 + tx*2;
    float acc[2][4] = {};
    const float* w2 = g_W2T + v;
    const float* hp = h1T + ty*4;
    #pragma unroll 4
    for (int k = 0; k < 256; k++){
        float2 w = *(const float2*)(w2 + (size_t)k*VOCP);
        float4 hv = *(const float4*)(hp + k*36);
        acc[0][0] = fmaf(w.x, hv.x, acc[0][0]);
        acc[0][1] = fmaf(w.x, hv.y, acc[0][1]);
        acc[0][2] = fmaf(w.x, hv.z, acc[0][2]);
        acc[0][3] = fmaf(w.x, hv.w, acc[0][3]);
        acc[1][0] = fmaf(w.y, hv.x, acc[1][0]);
        acc[1][1] = fmaf(w.y, hv.y, acc[1][1]);
        acc[1][2] = fmaf(w.y, hv.z, acc[1][2]);
        acc[1][3] = fmaf(w.y, hv.w, acc[1][3]);
    }
    float bv0 = (v < VOC)   ? b2[v]   : 0.f;
    float bv1 = (v+1 < VOC) ? b2[v+1] : 0.f;
    #pragma unroll
    for (int bb = 0; bb < 4; bb++){
        int b = b0 + ty*4 + bb;
        if (v < VOC)   g_logits[(size_t)b*VOC + v]   = acc[0][bb] + bv0;
        if (v+1 < VOC) g_logits[(size_t)b*VOC + v+1] = acc[1][bb] + bv1;
    }
}

// ------------- per-step softmax over VOC -----------------------------------
__global__ void k_soft(float* __restrict__ out, int t){
    int b = blockIdx.x, tid = threadIdx.x;   // 512
    __shared__ float buf[VOC];
    __shared__ float red[16];
    float m = -1e30f;
    for (int v = tid; v < VOC; v += 512){
        float x = g_logits[(size_t)b*VOC+v];
        buf[v] = x;
        m = fmaxf(m, x);
    }
    #pragma unroll
    for (int o=16;o;o>>=1) m = fmaxf(m, __shfl_xor_sync(0xffffffffu,m,o));
    if ((tid&31)==0) red[tid>>5]=m;
    __syncthreads();
    if (tid==0){ float mm=red[0]; for(int i=1;i<16;i++) mm=fmaxf(mm,red[i]); red[0]=mm; }
    __syncthreads();
    m = red[0];
    __syncthreads();
    float s = 0.f;
    for (int v = tid; v < VOC; v += 512){
        float e = fexp_(buf[v]-m);
        buf[v] = e;
        s += e;
    }
    #pragma unroll
    for (int o=16;o;o>>=1) s += __shfl_xor_sync(0xffffffffu,s,o);
    if ((tid&31)==0) red[tid>>5]=s;
    __syncthreads();
    if (tid==0){ float ss=0.f; for(int i=0;i<16;i++) ss+=red[i]; red[0]=1.f/ss; }
    __syncthreads();
    float inv = red[0];
    float* orow = out + ((size_t)b*T + t)*VOC;
    for (int v = tid; v < VOC; v += 512) orow[v] = buf[v]*inv;
}

// ---------------------------------------------------------------------------
extern "C" void kernel_launch(void* const* d_in, const int* in_sizes, int n_in,
                              void* d_out, int out_size){
    const float* features = (const float*)d_in[0];
    const int*   text     = (const int*)  d_in[1];
    const float* a0       = (const float*)d_in[2];
    const float* c0       = (const float*)d_in[3];
    const float* enc_W    = (const float*)d_in[4];
    const float* enc_b    = (const float*)d_in[5];
    const float* enc_g    = (const float*)d_in[6];
    const float* enc_beta = (const float*)d_in[7];
    const float* emb      = (const float*)d_in[8];
    const float* in_w     = (const float*)d_in[9];
    const float* in_b     = (const float*)d_in[10];
    const float* Wih      = (const float*)d_in[11];
    const float* Whh      = (const float*)d_in[12];
    const float* bih      = (const float*)d_in[13];
    const float* bhh      = (const float*)d_in[14];
    const float* ln_g     = (const float*)d_in[15];
    const float* ln_b     = (const float*)d_in[16];
    const float* W1       = (const float*)d_in[17];
    const float* b1       = (const float*)d_in[18];
    const float* W2       = (const float*)d_in[19];
    const float* b2       = (const float*)d_in[20];
    float* out = (float*)d_out;
    (void)in_sizes; (void)n_in; (void)out_size;

    cudaStream_t s0 = 0, sB;
    cudaStreamCreateWithFlags(&sB, cudaStreamNonBlocking);
    cudaEvent_t evF, evP, evL, evE, evQ0, evQ1;
    cudaEventCreateWithFlags(&evF, cudaEventDisableTiming);
    cudaEventCreateWithFlags(&evP, cudaEventDisableTiming);
    cudaEventCreateWithFlags(&evL, cudaEventDisableTiming);
    cudaEventCreateWithFlags(&evE, cudaEventDisableTiming);
    cudaEventCreateWithFlags(&evQ0, cudaEventDisableTiming);
    cudaEventCreateWithFlags(&evQ1, cudaEventDisableTiming);

    cudaEventRecord(evF, s0);
    cudaStreamWaitEvent(sB, evF, 0);

    k_encoder<<<G, 256, 0, s0>>>(features, enc_W, enc_b, enc_g, enc_beta);   // 0
    k_qkf<<<dim3(BS*G/60, 4), 272, 0, s0>>>(in_w);                           // 1
    k_prepT<<<dim3(17, 157, 4), dim3(32, 8), 0, sB>>>(in_w, Wih, Whh, W2);   // 2
    k_aexp<<<dim3(6, 6, BS*H), 256, 0, s0>>>();                              // 3 (profiled)
    k_prepS<<<(BS*U + 255)/256, 256, 0, sB>>>(bih, bhh, a0, c0);             // 4
    cudaEventRecord(evP, sB);
    cudaStreamWaitEvent(s0, evP, 0);

    for (int t = 0; t < T; t++){
        int par = t & 1;
        // WAR: attF(t) overwrites a[par], last read by mlp1 issued in iter t-2
        if (t >= 3) cudaStreamWaitEvent(s0, (par == 0) ? evQ0 : evQ1, 0);
        k_attF<<<BS*H, 384, 0, s0>>>(in_b, ln_g, ln_b, t);   // contains lstm(t-1)
        if (t >= 1){
            cudaEventRecord(evL, s0);
            cudaStreamWaitEvent(sB, evL, 0);
            k_mlp1<<<BS, 512, 0, sB>>>(W1, b1, par);          // step t-1 output uses a_t
            cudaEventRecord((par == 0) ? evQ0 : evQ1, sB);
            k_mlp2<<<dim3((VOC+63)/64, 2), 256, 0, sB>>>(b2);
            k_soft<<<BS, 512, 0, sB>>>(out, t - 1);
        }
        k_gates<<<dim3(16, 8, 2), 128, 0, s0>>>(text, emb, out, t, par);
    }
    // final lstm(T-1) -> a_T (parity T&1 = 1), then last step's output on sB
    cudaStreamWaitEvent(s0, evQ1, 0);     // a[1] last read by mlp1 of iter 13
    k_lstmF<<<BS, 512, 0, s0>>>(ln_g, ln_b, (T-1)&1, T&1);
    cudaEventRecord(evL, s0);
    cudaStreamWaitEvent(sB, evL, 0);
    k_mlp1<<<BS, 512, 0, sB>>>(W1, b1, T&1);
    k_mlp2<<<dim3((VOC+63)/64, 2), 256, 0, sB>>>(b2);
    k_soft<<<BS, 512, 0, sB>>>(out, T-1);
    cudaEventRecord(evE, sB);
    cudaStreamWaitEvent(s0, evE, 0);
}

// round 16
// speedup vs baseline: 1.4914x; 1.2684x over previous
#include <cuda_runtime.h>
#include <cuda_fp16.h>

#define BS 64
#define G 360
#define V 100
#define D 32
#define U 512
#define T 15
#define VOC 5000
#define VOCP 5120
#define TD 512
#define H 8
#define E 544          // D + U
#define HD 68          // E / H
#define NEG 0.2f
#define INV_S 0.12126781251816648f   // 1/sqrt(68)
#define XDIM 1056      // E + U
#define XH 528         // XDIM/2 (split-K half)
#define R4U 2048       // 4*U

// ----------------------------- device scratch -----------------------------
__device__ float  g_feat[BS*G*D];
__device__ float  g_qf[(size_t)BS*G*E];
__device__ float  g_kf[(size_t)BS*G*E];
__device__ __half g_Ebuf[(size_t)BS*H*G*G];   // fp16 exp(A), shift-free
__device__ float  g_WqaT[U*E];
__device__ float  g_Wcat[(size_t)XDIM*R4U];
__device__ float  g_bias[R4U];
__device__ float  g_W2T[256*VOCP];            // fp32 W2^T, padded tail zeroed
__device__ float  g_wpart[BS*H*G];
__device__ float  g_ctxp[BS*H*D];             // per-head partial ctx
__device__ float  g_gates[BS*R4U];
__device__ float  g_gates2[BS*R4U];
__device__ float  g_ab[2*BS*U];               // double-buffered hidden state a
__device__ float  g_cb[2*BS*U];               // double-buffered cell state c
__device__ float  g_h1b[2*BS*256];            // double-buffered h1
__device__ float  g_logits[BS*VOC];

__device__ __forceinline__ float sigmoidf_(float x){ return 1.f/(1.f+__expf(-x)); }
__device__ __forceinline__ float leakyf_(float x){ return x > 0.f ? x : NEG*x; }

__device__ __forceinline__ float fexp_(float x){
    float t = x * 1.4426950408889634f;
    float r = rintf(t);
    float f = t - r;
    float p =          1.3333558e-3f;
    p = fmaf(p, f, 9.6181291e-3f);
    p = fmaf(p, f, 5.5504109e-2f);
    p = fmaf(p, f, 2.4022651e-1f);
    p = fmaf(p, f, 6.9314718e-1f);
    p = fmaf(p, f, 1.0f);
    int ei = (int)r;
    if (ei < -126) ei = -126;
    return p * __int_as_float((ei + 127) << 23);
}

// ---------------------- encoder: feat = lrelu(LN(x@W+b)) -------------------
__global__ void k_encoder(const float* __restrict__ features, const float* __restrict__ enc_W,
                          const float* __restrict__ enc_b, const float* __restrict__ enc_g,
                          const float* __restrict__ enc_beta){
    int g = blockIdx.x;
    int tid = threadIdx.x;               // 256
    int warp = tid >> 5, lane = tid & 31;
    __shared__ float Ws[D*101];
    __shared__ float bs_[D];
    __shared__ float xw[8][V];
    for (int k = tid; k < D*V; k += 256){
        int d = k / V, v = k - d*V;
        Ws[d*101 + v] = enc_W[(size_t)g*D*V + k];
    }
    if (tid < D) bs_[tid] = enc_b[g*D + tid];
    __syncthreads();
    float gg = enc_g[lane], bb = enc_beta[lane];
    for (int b = warp; b < BS; b += 8){
        for (int v = lane; v < V; v += 32) xw[warp][v] = features[((size_t)b*G + g)*V + v];
        __syncwarp();
        const float* w = Ws + lane*101;
        float acc = bs_[lane];
        #pragma unroll 4
        for (int v = 0; v < V; v++) acc = fmaf(xw[warp][v], w[v], acc);
        float m = acc;
        #pragma unroll
        for (int o=16;o;o>>=1) m += __shfl_xor_sync(0xffffffffu, m, o);
        m *= (1.f/32.f);
        float dv = acc - m, vv = dv*dv;
        #pragma unroll
        for (int o=16;o;o>>=1) vv += __shfl_xor_sync(0xffffffffu, vv, o);
        vv *= (1.f/32.f);
        float y = dv*rsqrtf(vv+1e-5f)*gg + bb;
        g_feat[((size_t)b*G + g)*D + lane] = leakyf_(y);
        __syncwarp();
    }
}

// ---------------- qf / kf projections (weights in registers) ---------------
__global__ void k_qkf(const float* __restrict__ in_w){
    int mat = blockIdx.y >> 1;
    int eh  = blockIdx.y & 1;
    int le  = threadIdx.x;               // 0..271
    int ebase = eh*272;
    __shared__ float Ws[272*33];
    __shared__ float fs[60*32];
    for (int k = le; k < 272*32; k += 272){
        int i = k >> 5, d = k & 31;
        Ws[i*33 + d] = in_w[((size_t)(mat*E + ebase + i))*E + d];
    }
    int r0 = blockIdx.x*60;
    for (int k = le; k < 60*32; k += 272)
        fs[k] = g_feat[(size_t)r0*D + k];
    __syncthreads();
    float w[32];
    #pragma unroll
    for (int d = 0; d < 32; d++) w[d] = Ws[le*33 + d];
    float* dst = (mat == 0 ? g_qf : g_kf);
    #pragma unroll 2
    for (int rr = 0; rr < 60; rr++){
        float acc = 0.f;
        #pragma unroll
        for (int d = 0; d < 32; d++) acc = fmaf(fs[rr*32 + d], w[d], acc);
        dst[(size_t)(r0 + rr)*E + ebase + le] = acc;
    }
}

// -------- coalesced weight transposes (32x32 smem tiles, z = matrix) --------
__global__ void k_prepT(const float* __restrict__ in_w, const float* __restrict__ Wih,
                        const float* __restrict__ Whh, const float* __restrict__ W2){
    __shared__ float tile[32][33];
    int zz = blockIdx.z;
    int c0 = blockIdx.x*32, r0 = blockIdx.y*32;
    int tx = threadIdx.x, ty = threadIdx.y;  // 32 x 8
    int R, C, ld, off, dstld;
    const float* src; float* dst;
    if (zz == 0){ R = E;   C = U;   src = in_w; ld = E;   off = D; dst = g_WqaT;           dstld = E;   }
    else if (zz == 1){ R = R4U; C = E; src = Wih; ld = E; off = 0; dst = g_Wcat;           dstld = R4U; }
    else if (zz == 2){ R = R4U; C = U; src = Whh; ld = U; off = 0; dst = g_Wcat + (size_t)E*R4U; dstld = R4U; }
    else { R = VOC; C = 256; src = W2;  ld = 256; off = 0; dst = g_W2T;                    dstld = VOCP; }
    if (r0 >= R || c0 >= C) return;
    for (int i = ty; i < 32; i += 8){
        int r = r0 + i, c = c0 + tx;
        if (r < R && c < C) tile[i][tx] = src[(size_t)r*ld + off + c];
    }
    __syncthreads();
    for (int i = ty; i < 32; i += 8){
        int c = c0 + i, r = r0 + tx;
        if (c < C && r < R) dst[(size_t)c*dstld + r] = tile[tx][i];
    }
}

// -------- small prep: bias sum, a/c init, W2T pad-zero ----------------------
__global__ void k_prepS(const float* __restrict__ bih, const float* __restrict__ bhh,
                        const float* __restrict__ a0, const float* __restrict__ c0){
    int i = blockIdx.x*256 + threadIdx.x;
    if (i < R4U) g_bias[i] = bih[i] + bhh[i];
    if (i < BS*U){ g_ab[i] = a0[i]; g_cb[i] = c0[i]; }
    if (i < 256*(VOCP-VOC)){
        int k = i / (VOCP-VOC), v = VOC + (i - k*(VOCP-VOC));
        g_W2T[(size_t)k*VOCP + v] = 0.f;
    }
}

// -- A-GEMM (HFMA2) with exp epilogue: E[b,h,i,j] = exp(qf.kf/sqrt(HD)) fp16 -
__global__ void k_aexp(){
    int bh = blockIdx.z; int b = bh >> 3, h = bh & 7;
    int i0 = blockIdx.y << 6, j0 = blockIdx.x << 6;
    __shared__ __half2 Qs[34*68];
    __shared__ __half2 Ks[34*68];
    int tid = threadIdx.x;             // 256
    const float* qbase = g_qf + (size_t)(b*G)*E + h*HD;
    for (int k = tid; k < 64*34; k += 256){
        int ii = k / 34, dp = k - ii*34;
        int gi = i0 + ii;
        float x0 = 0.f, x1 = 0.f;
        if (gi < G){
            x0 = qbase[(size_t)gi*E + 2*dp];
            x1 = qbase[(size_t)gi*E + 2*dp + 1];
        }
        Qs[dp*68 + ii] = __floats2half2_rn(x0, x1);
    }
    const float* kbase = g_kf + (size_t)(b*G)*E + h*HD;
    for (int k = tid; k < 64*34; k += 256){
        int jj = k / 34, dp = k - jj*34;
        int gj = j0 + jj;
        float x0 = 0.f, x1 = 0.f;
        if (gj < G){
            x0 = kbase[(size_t)gj*E + 2*dp];
            x1 = kbase[(size_t)gj*E + 2*dp + 1];
        }
        Ks[dp*68 + jj] = __floats2half2_rn(x0, x1);
    }
    __syncthreads();
    int tx = tid & 15, ty = tid >> 4;
    __half2 acc[4][4];
    #pragma unroll
    for (int r = 0; r < 4; r++)
        #pragma unroll
        for (int c = 0; c < 4; c++) acc[r][c] = __floats2half2_rn(0.f, 0.f);
    #pragma unroll 2
    for (int dp = 0; dp < 34; dp++){
        float4 qv = *(const float4*)&Qs[dp*68 + (ty<<2)];
        float4 kv = *(const float4*)&Ks[dp*68 + (tx<<2)];
        __half2 q2[4], k2[4];
        q2[0] = *(__half2*)&qv.x; q2[1] = *(__half2*)&qv.y;
        q2[2] = *(__half2*)&qv.z; q2[3] = *(__half2*)&qv.w;
        k2[0] = *(__half2*)&kv.x; k2[1] = *(__half2*)&kv.y;
        k2[2] = *(__half2*)&kv.z; k2[3] = *(__half2*)&kv.w;
        #pragma unroll
        for (int r = 0; r < 4; r++)
            #pragma unroll
            for (int c = 0; c < 4; c++) acc[r][c] = __hfma2(q2[r], k2[c], acc[r][c]);
    }
    #pragma unroll
    for (int r = 0; r < 4; r++){
        int i = i0 + (ty<<2) + r;
        if (i >= G) continue;
        __half* row = g_Ebuf + ((size_t)bh*G + i)*G;
        #pragma unroll
        for (int c = 0; c < 4; c += 2){
            int j = j0 + (tx<<2) + c;
            float a0v = __low2float(acc[r][c])   + __high2float(acc[r][c]);
            float a1v = __low2float(acc[r][c+1]) + __high2float(acc[r][c+1]);
            if (j + 1 < G){
                *(__half2*)(row + j) = __floats2half2_rn(fexp_(a0v*INV_S), fexp_(a1v*INV_S));
            } else if (j < G){
                row[j] = __float2half(fexp_(a0v*INV_S));
            }
        }
    }
}

// == fused per-step kernel: [lstm(t-1) if t>0] + qa + e + E-pass + ctxp ======
__global__ void k_attF(const float* __restrict__ in_b, const float* __restrict__ ln_g,
                       const float* __restrict__ ln_bv, int t){
    int bh = blockIdx.x; int b = bh >> 3, h = bh & 7;
    int tid = threadIdx.x;               // 384
    int warp = tid >> 5, lane = tid & 31;
    __shared__ float as_[U];
    __shared__ float qp[4][HD];
    __shared__ float qs[HD];
    __shared__ float es[G];
    __shared__ float wp_s[G];
    __shared__ float colsum[12][G];
    __shared__ float r1[12], r2[12];
    int par = t & 1;
    if (t == 0){
        for (int u = tid; u < U; u += 384) as_[u] = g_ab[b*U + u];
        __syncthreads();
    } else {
        int cin = (t - 1) & 1;
        const float* gr0 = g_gates  + (size_t)b*R4U;
        const float* gr1 = g_gates2 + (size_t)b*R4U;
        float hhv[2]; int nown = (tid < 128) ? 2 : 1;
        float s1 = 0.f, s2 = 0.f;
        #pragma unroll
        for (int k = 0; k < 2; k++){
            if (k < nown){
                int u = tid + k*384;
                float gi = gr0[u]       + gr1[u]       + g_bias[u];
                float gf = gr0[U+u]     + gr1[U+u]     + g_bias[U+u];
                float gg = gr0[2*U+u]   + gr1[2*U+u]   + g_bias[2*U+u];
                float go = gr0[3*U+u]   + gr1[3*U+u]   + g_bias[3*U+u];
                float c = sigmoidf_(gf)*g_cb[(size_t)cin*BS*U + b*U + u] + sigmoidf_(gi)*tanhf(gg);
                g_cb[(size_t)par*BS*U + b*U + u] = c;
                float hh = sigmoidf_(go)*tanhf(c);
                hhv[k] = hh;
                s1 += hh; s2 += hh*hh;
            }
        }
        #pragma unroll
        for (int o=16;o;o>>=1){ s1 += __shfl_xor_sync(0xffffffffu,s1,o); s2 += __shfl_xor_sync(0xffffffffu,s2,o); }
        if (lane == 0){ r1[warp] = s1; r2[warp] = s2; }
        __syncthreads();
        if (tid == 0){
            float t1 = 0.f, t2 = 0.f;
            #pragma unroll
            for (int i = 0; i < 12; i++){ t1 += r1[i]; t2 += r2[i]; }
            r1[0] = t1; r2[0] = t2;
        }
        __syncthreads();
        float m = r1[0]*(1.f/(float)U);
        float var = r2[0]*(1.f/(float)U) - m*m;
        float rstd = rsqrtf(var + 1e-5f);
        #pragma unroll
        for (int k = 0; k < 2; k++){
            if (k < nown){
                int u = tid + k*384;
                float a = (hhv[k] - m)*rstd*ln_g[u] + ln_bv[u];
                as_[u] = a;
                g_ab[(size_t)par*BS*U + b*U + u] = a;
            }
        }
        __syncthreads();
    }
    if (tid < 272){
        int d = tid % HD, part = tid / HD;
        const float* wcol = g_WqaT + h*HD + d;
        float acc = 0.f;
        int u0 = part*128;
        #pragma unroll 8
        for (int u = 0; u < 128; u++) acc = fmaf(as_[u0+u], wcol[(size_t)(u0+u)*E], acc);
        qp[part][d] = acc;
    }
    __syncthreads();
    if (tid < HD) qs[tid] = qp[0][tid]+qp[1][tid]+qp[2][tid]+qp[3][tid] + in_b[h*HD + tid];
    __syncthreads();
    for (int jr = warp; jr < G; jr += 12){
        const float* kfr = g_kf + ((size_t)(b*G + jr))*E + h*HD;
        float p = kfr[lane]*qs[lane] + kfr[lane+32]*qs[lane+32];
        if (lane < 4) p = fmaf(kfr[64+lane], qs[64+lane], p);
        #pragma unroll
        for (int o=16;o;o>>=1) p += __shfl_xor_sync(0xffffffffu, p, o);
        if (lane == 0) es[jr] = fexp_(p * INV_S);
    }
    __syncthreads();
    float racc[12];
    #pragma unroll
    for (int k = 0; k < 12; k++) racc[k] = 0.f;
    const __half2* Eb = (const __half2*)(g_Ebuf + (size_t)bh*G*G);
    const float2* es2 = (const float2*)es;
    for (int i = warp*2; i < G; i += 24){
        const __half2* r0p = Eb + (size_t)i*(G/2);
        const __half2* r1p = r0p + (G/2);
        float2 f0[6], f1[6];
        float d0 = 0.f, d1 = 0.f;
        #pragma unroll
        for (int s = 0; s < 6; s++){
            int jj = lane + 32*s;
            if (jj < G/2){
                f0[s] = __half22float2(r0p[jj]);
                f1[s] = __half22float2(r1p[jj]);
                float2 e2 = es2[jj];
                d0 = fmaf(f0[s].x, e2.x, d0);
                d0 = fmaf(f0[s].y, e2.y, d0);
                d1 = fmaf(f1[s].x, e2.x, d1);
                d1 = fmaf(f1[s].y, e2.y, d1);
            } else {
                f0[s].x = 0.f; f0[s].y = 0.f;
                f1[s].x = 0.f; f1[s].y = 0.f;
            }
        }
        #pragma unroll
        for (int o=16;o;o>>=1){
            d0 += __shfl_xor_sync(0xffffffffu, d0, o);
            d1 += __shfl_xor_sync(0xffffffffu, d1, o);
        }
        float rinv0 = 1.f/d0, rinv1 = 1.f/d1;
        #pragma unroll
        for (int s = 0; s < 6; s++){
            racc[2*s]   = fmaf(f0[s].x, rinv0, fmaf(f1[s].x, rinv1, racc[2*s]));
            racc[2*s+1] = fmaf(f0[s].y, rinv0, fmaf(f1[s].y, rinv1, racc[2*s+1]));
        }
    }
    #pragma unroll
    for (int s = 0; s < 6; s++){
        int jj = lane + 32*s;
        if (jj < G/2){
            colsum[warp][2*jj]   = racc[2*s];
            colsum[warp][2*jj+1] = racc[2*s+1];
        }
    }
    __syncthreads();
    if (tid < G){
        float tot = 0.f;
        #pragma unroll
        for (int w = 0; w < 12; w++) tot += colsum[w][tid];
        float wv = es[tid]*tot;
        wp_s[tid] = wv;
        g_wpart[bh*G + tid] = wv;
    }
    __syncthreads();
    {
        int j0 = warp*30;
        const float* fp = g_feat + ((size_t)b*G + j0)*D + lane;
        float acc = 0.f;
        #pragma unroll 5
        for (int j = 0; j < 30; j++) acc = fmaf(wp_s[j0 + j], fp[(size_t)j*D], acc);
        colsum[warp][lane] = acc;
    }
    __syncthreads();
    if (tid < D){
        float s = 0.f;
        #pragma unroll
        for (int k = 0; k < 12; k++) s += colsum[k][tid];
        g_ctxp[bh*D + tid] = s;
    }
}

// ---- per-step: gate GEMM + scores out + ctx + (z=1) fused MLP1 -------------
__global__ void k_gates(const int* __restrict__ text, const float* __restrict__ emb,
                        float* __restrict__ out, const float* __restrict__ W1,
                        const float* __restrict__ b1, int t, int par){
    int z  = blockIdx.z;
    int b0 = blockIdx.y*8;
    int tid = threadIdx.x;               // 128
    int r = blockIdx.x*128 + tid;        // grid.x = 16
    __shared__ float xs[8][XH];
    int x0 = z*XH;
    const float* ga = g_ab + (size_t)par*BS*U;
    if (z == 0){
        if (blockIdx.x == 0){
            for (int idx = tid; idx < 8*G; idx += 128){
                int bb = idx / G, j = idx - bb*G;
                const float* p = g_wpart + (size_t)(b0+bb)*H*G + j;
                float acc = 0.f;
                #pragma unroll
                for (int hh = 0; hh < H; hh++) acc += p[hh*G];
                out[(size_t)BS*T*VOC + ((size_t)(b0+bb)*T + t)*G + j] = acc * (1.f/(float)(H*G));
            }
        }
        for (int pr = tid; pr < 256; pr += 128){
            int bb = pr >> 5, d = pr & 31;
            const float* cp = g_ctxp + (size_t)(b0+bb)*H*D + d;
            float acc = 0.f;
            #pragma unroll
            for (int hh = 0; hh < H; hh++) acc += cp[hh*D];
            xs[bb][d] = acc * (1.f/(float)(H*G));
        }
        for (int bb = 0; bb < 8; bb++){
            int b = b0 + bb;
            int tok = text[b*T + t];
            for (int xx = tid; xx < XH; xx += 128){
                if (xx >= D) xs[bb][xx] = emb[(size_t)tok*TD + (xx - D)];
            }
        }
    } else {
        for (int bb = 0; bb < 8; bb++){
            int b = b0 + bb;
            int tok = text[b*T + t];
            for (int xx = tid; xx < XH; xx += 128){
                int x = x0 + xx;
                xs[bb][xx] = (x < E) ? emb[(size_t)tok*TD + (x - D)] : ga[b*U + (x - E)];
            }
        }
    }
    __syncthreads();
    float acc[8] = {};
    const float* wp = g_Wcat + (size_t)x0*R4U + r;
    #pragma unroll 4
    for (int xx = 0; xx < XH; xx++){
        float w = wp[(size_t)xx*R4U];
        #pragma unroll
        for (int bb = 0; bb < 8; bb++) acc[bb] = fmaf(xs[bb][xx], w, acc[bb]);
    }
    float* dst = (z == 0) ? g_gates : g_gates2;
    #pragma unroll
    for (int bb = 0; bb < 8; bb++) dst[(size_t)(b0+bb)*R4U + r] = acc[bb];
    // ---- fused MLP1 (z=1 blocks hold a(t) in xs[.][16..527]) -------------
    if (z == 1){
        int w = tid >> 5, l = tid & 31;  // 4 warps x 4 k's = 16 k per block
        #pragma unroll
        for (int kk = 0; kk < 4; kk++){
            int k = blockIdx.x*16 + w*4 + kk;
            const float* wrow = W1 + (size_t)k*U;
            float wreg[16];
            #pragma unroll
            for (int i = 0; i < 16; i++) wreg[i] = wrow[l + 32*i];
            #pragma unroll
            for (int bb = 0; bb < 8; bb++){
                float acc1 = 0.f;
                #pragma unroll
                for (int i = 0; i < 16; i++)
                    acc1 = fmaf(leakyf_(xs[bb][16 + l + 32*i]), wreg[i], acc1);
                #pragma unroll
                for (int o=16;o;o>>=1) acc1 += __shfl_xor_sync(0xffffffffu, acc1, o);
                if (l == 0)
                    g_h1b[(size_t)par*BS*256 + (size_t)(b0+bb)*256 + k] = leakyf_(acc1 + b1[k]);
            }
        }
    }
}

// ------------- final LSTM cell + LN (only for t = T-1) ----------------------
__global__ void k_lstmF(const float* __restrict__ ln_g, const float* __restrict__ ln_b,
                        int cin, int outpar){
    int b = blockIdx.x, tid = threadIdx.x;   // 512
    __shared__ float r1[16], r2[16];
    int u = tid;
    const float* gr0 = g_gates  + (size_t)b*R4U;
    const float* gr1 = g_gates2 + (size_t)b*R4U;
    float gi = gr0[u]       + gr1[u]       + g_bias[u];
    float gf = gr0[U+u]     + gr1[U+u]     + g_bias[U+u];
    float gg = gr0[2*U+u]   + gr1[2*U+u]   + g_bias[2*U+u];
    float go = gr0[3*U+u]   + gr1[3*U+u]   + g_bias[3*U+u];
    float c = sigmoidf_(gf)*g_cb[(size_t)cin*BS*U + b*U + u] + sigmoidf_(gi)*tanhf(gg);
    g_cb[(size_t)outpar*BS*U + b*U + u] = c;
    float hh = sigmoidf_(go)*tanhf(c);
    float s1 = hh, s2 = hh*hh;
    #pragma unroll
    for (int o=16;o;o>>=1){ s1 += __shfl_xor_sync(0xffffffffu,s1,o); s2 += __shfl_xor_sync(0xffffffffu,s2,o); }
    int w = tid>>5, l = tid&31;
    if (l==0){ r1[w]=s1; r2[w]=s2; }
    __syncthreads();
    if (tid==0){
        float t1=0.f, t2=0.f;
        #pragma unroll
        for (int i=0;i<16;i++){ t1+=r1[i]; t2+=r2[i]; }
        r1[0]=t1; r2[0]=t2;
    }
    __syncthreads();
    float m = r1[0]*(1.f/(float)U);
    float var = r2[0]*(1.f/(float)U) - m*m;
    float a = (hh-m)*rsqrtf(var+1e-5f)*ln_g[u]+ln_b[u];
    g_ab[(size_t)outpar*BS*U + b*U + u] = a;
}

// ------------- tail MLP layer 1 (once, on stream B) -------------------------
__global__ void k_mlp1(const float* __restrict__ W1, const float* __restrict__ b1, int par){
    int b = blockIdx.x, tid = threadIdx.x;   // 512
    __shared__ float sact[U];
    sact[tid] = leakyf_(g_ab[(size_t)par*BS*U + b*U + tid]);
    __syncthreads();
    int w = tid>>5, l = tid&31;
    #pragma unroll
    for (int kk = 0; kk < 16; kk++){
        int k = w*16 + kk;
        const float* wrow = W1 + (size_t)k*U;
        float acc = 0.f;
        #pragma unroll 4
        for (int uu = l; uu < U; uu += 32) acc = fmaf(sact[uu], wrow[uu], acc);
        #pragma unroll
        for (int o=16;o;o>>=1) acc += __shfl_xor_sync(0xffffffffu, acc, o);
        if (l==0) g_h1b[(size_t)par*BS*256 + b*256+k] = leakyf_(acc + b1[k]);
    }
}

// ------------- per-step MLP layer 2 (register-blocked GEMM) ----------------
__global__ void k_mlp2(const float* __restrict__ b2, int par){
    int v0 = blockIdx.x*64;
    int b0 = blockIdx.y*32;
    int tid = threadIdx.x;                   // 256
    int tx = tid & 31, ty = tid >> 5;
    __shared__ float h1T[256*36];
    const float* h1 = g_h1b + (size_t)par*BS*256;
    for (int i = tid; i < 256*32; i += 256){
        int k = i & 255, bb = i >> 8;
        h1T[k*36 + bb] = h1[(size_t)(b0+bb)*256 + k];
    }
    __syncthreads();
    int v = v0 + tx*2;
    float acc[2][4] = {};
    const float* w2 = g_W2T + v;
    const float* hp = h1T + ty*4;
    #pragma unroll 4
    for (int k = 0; k < 256; k++){
        float2 w = *(const float2*)(w2 + (size_t)k*VOCP);
        float4 hv = *(const float4*)(hp + k*36);
        acc[0][0] = fmaf(w.x, hv.x, acc[0][0]);
        acc[0][1] = fmaf(w.x, hv.y, acc[0][1]);
        acc[0][2] = fmaf(w.x, hv.z, acc[0][2]);
        acc[0][3] = fmaf(w.x, hv.w, acc[0][3]);
        acc[1][0] = fmaf(w.y, hv.x, acc[1][0]);
        acc[1][1] = fmaf(w.y, hv.y, acc[1][1]);
        acc[1][2] = fmaf(w.y, hv.z, acc[1][2]);
        acc[1][3] = fmaf(w.y, hv.w, acc[1][3]);
    }
    float bv0 = (v < VOC)   ? b2[v]   : 0.f;
    float bv1 = (v+1 < VOC) ? b2[v+1] : 0.f;
    #pragma unroll
    for (int bb = 0; bb < 4; bb++){
        int b = b0 + ty*4 + bb;
        if (v < VOC)   g_logits[(size_t)b*VOC + v]   = acc[0][bb] + bv0;
        if (v+1 < VOC) g_logits[(size_t)b*VOC + v+1] = acc[1][bb] + bv1;
    }
}

// ------------- per-step softmax over VOC -----------------------------------
__global__ void k_soft(float* __restrict__ out, int t){
    int b = blockIdx.x, tid = threadIdx.x;   // 512
    __shared__ float buf[VOC];
    __shared__ float red[16];
    float m = -1e30f;
    for (int v = tid; v < VOC; v += 512){
        float x = g_logits[(size_t)b*VOC+v];
        buf[v] = x;
        m = fmaxf(m, x);
    }
    #pragma unroll
    for (int o=16;o;o>>=1) m = fmaxf(m, __shfl_xor_sync(0xffffffffu,m,o));
    if ((tid&31)==0) red[tid>>5]=m;
    __syncthreads();
    if (tid==0){ float mm=red[0]; for(int i=1;i<16;i++) mm=fmaxf(mm,red[i]); red[0]=mm; }
    __syncthreads();
    m = red[0];
    __syncthreads();
    float s = 0.f;
    for (int v = tid; v < VOC; v += 512){
        float e = fexp_(buf[v]-m);
        buf[v] = e;
        s += e;
    }
    #pragma unroll
    for (int o=16;o;o>>=1) s += __shfl_xor_sync(0xffffffffu,s,o);
    if ((tid&31)==0) red[tid>>5]=s;
    __syncthreads();
    if (tid==0){ float ss=0.f; for(int i=0;i<16;i++) ss+=red[i]; red[0]=1.f/ss; }
    __syncthreads();
    float inv = red[0];
    float* orow = out + ((size_t)b*T + t)*VOC;
    for (int v = tid; v < VOC; v += 512) orow[v] = buf[v]*inv;
}

// ---------------------------------------------------------------------------
extern "C" void kernel_launch(void* const* d_in, const int* in_sizes, int n_in,
                              void* d_out, int out_size){
    const float* features = (const float*)d_in[0];
    const int*   text     = (const int*)  d_in[1];
    const float* a0       = (const float*)d_in[2];
    const float* c0       = (const float*)d_in[3];
    const float* enc_W    = (const float*)d_in[4];
    const float* enc_b    = (const float*)d_in[5];
    const float* enc_g    = (const float*)d_in[6];
    const float* enc_beta = (const float*)d_in[7];
    const float* emb      = (const float*)d_in[8];
    const float* in_w     = (const float*)d_in[9];
    const float* in_b     = (const float*)d_in[10];
    const float* Wih      = (const float*)d_in[11];
    const float* Whh      = (const float*)d_in[12];
    const float* bih      = (const float*)d_in[13];
    const float* bhh      = (const float*)d_in[14];
    const float* ln_g     = (const float*)d_in[15];
    const float* ln_b     = (const float*)d_in[16];
    const float* W1       = (const float*)d_in[17];
    const float* b1       = (const float*)d_in[18];
    const float* W2       = (const float*)d_in[19];
    const float* b2       = (const float*)d_in[20];
    float* out = (float*)d_out;
    (void)in_sizes; (void)n_in; (void)out_size;

    cudaStream_t s0 = 0, sB;
    cudaStreamCreateWithFlags(&sB, cudaStreamNonBlocking);
    cudaEvent_t evF, evP, evL, evE, evM0, evM1;
    cudaEventCreateWithFlags(&evF, cudaEventDisableTiming);
    cudaEventCreateWithFlags(&evP, cudaEventDisableTiming);
    cudaEventCreateWithFlags(&evL, cudaEventDisableTiming);
    cudaEventCreateWithFlags(&evE, cudaEventDisableTiming);
    cudaEventCreateWithFlags(&evM0, cudaEventDisableTiming);
    cudaEventCreateWithFlags(&evM1, cudaEventDisableTiming);

    cudaEventRecord(evF, s0);
    cudaStreamWaitEvent(sB, evF, 0);

    k_encoder<<<G, 256, 0, s0>>>(features, enc_W, enc_b, enc_g, enc_beta);   // 0
    k_qkf<<<dim3(BS*G/60, 4), 272, 0, s0>>>(in_w);                           // 1
    k_prepT<<<dim3(17, 157, 4), dim3(32, 8), 0, sB>>>(in_w, Wih, Whh, W2);   // 2
    k_aexp<<<dim3(6, 6, BS*H), 256, 0, s0>>>();                              // 3 (profiled)
    k_prepS<<<(BS*U + 255)/256, 256, 0, sB>>>(bih, bhh, a0, c0);             // 4
    cudaEventRecord(evP, sB);
    cudaStreamWaitEvent(s0, evP, 0);

    for (int t = 0; t < T; t++){
        int par = t & 1;
        k_attF<<<BS*H, 384, 0, s0>>>(in_b, ln_g, ln_b, t);   // contains lstm(t-1)
        // WAR: gates(t) writes h1[par], last read by mlp2 launched at iter t-2
        if (t >= 3) cudaStreamWaitEvent(s0, (par == 0) ? evM0 : evM1, 0);
        k_gates<<<dim3(16, 8, 2), 128, 0, s0>>>(text, emb, out, W1, b1, t, par);
        if (t >= 1){
            cudaEventRecord(evL, s0);
            cudaStreamWaitEvent(sB, evL, 0);
            k_mlp2<<<dim3((VOC+63)/64, 2), 256, 0, sB>>>(b2, par);
            cudaEventRecord((par == 0) ? evM0 : evM1, sB);
            k_soft<<<BS, 512, 0, sB>>>(out, t - 1);
        }
    }
    // tail: lstm(T-1) -> a_T (parity 1), h1, logits, out(T-1)
    k_lstmF<<<BS, 512, 0, s0>>>(ln_g, ln_b, (T-1)&1, T&1);
    cudaEventRecord(evL, s0);
    cudaStreamWaitEvent(sB, evL, 0);
    k_mlp1<<<BS, 512, 0, sB>>>(W1, b1, T&1);
    k_mlp2<<<dim3((VOC+63)/64, 2), 256, 0, sB>>>(b2, T&1);
    k_soft<<<BS, 512, 0, sB>>>(out, T-1);
    cudaEventRecord(evE, sB);
    cudaStreamWaitEvent(s0, evE, 0);
}